// round 12
// baseline (speedup 1.0000x reference)
#include <cuda_runtime.h>
#include <cuda_bf16.h>
#include <cstdint>
#include <math.h>

#define B_ 2
#define T_ 2048
#define BT 4096
#define C_ 1024
#define V_ 32000
#define L_ 4
#define E_ 3
#define H_ 4096
#define NCH 32
#define CHL 64
#define SZ (BT*C_)

typedef __nv_bfloat16 bf16;

// ---------------- static scratch (no allocations) ----------------
__device__ float g_X[SZ], g_HS[SZ], g_R[SZ], g_Kb[SZ], g_Vb[SZ], g_ST[SZ], g_Hh[SZ];
__device__ float g_EC[SZ];
__device__ float g_FF[(size_t)BT * H_];
__device__ float g_PART[B_ * NCH * C_], g_SCL[BT];
__device__ int   g_WIN[BT];
__device__ int   g_CNT[E_];
__device__ int   g_LIST[E_][BT];

__device__ bf16 g_MIXb[2][SZ], g_RSb[2][SZ], g_Hb[2][SZ], g_STb[2][SZ], g_HSb[2][SZ];
__device__ bf16 g_GA[2][SZ];
__device__ bf16 g_GS[2][SZ];
__device__ bf16 g_FFb[2][(size_t)BT * H_];

__device__ bf16 g_WrT[2][(size_t)L_ * C_ * C_], g_WkT[2][(size_t)L_ * C_ * C_];
__device__ bf16 g_WvT[2][(size_t)L_ * C_ * C_], g_WoT[2][(size_t)L_ * C_ * C_];
__device__ bf16 g_W1T[2][(size_t)L_ * 2 * H_ * C_], g_W2T[2][(size_t)L_ * 2 * C_ * H_];
__device__ bf16 g_Wl1T[2][(size_t)L_ * H_ * 2 * C_], g_Wl2T[2][(size_t)L_ * C_ * H_];
__device__ bf16 g_HT[2][(size_t)V_ * C_];

__device__ __forceinline__ void split2(float x, bf16& h, bf16& l) {
    h = __float2bfloat16(x);
    l = __float2bfloat16(x - __bfloat162float(h));
}

// ---------------- block reduce / LN ----------------
__device__ __forceinline__ float blockReduceSum(float val) {
    __shared__ float sh[8];
    int lane = threadIdx.x & 31, w = threadIdx.x >> 5;
#pragma unroll
    for (int o = 16; o > 0; o >>= 1) val += __shfl_xor_sync(0xffffffffu, val, o);
    if (lane == 0) sh[w] = val;
    __syncthreads();
    if (w == 0) {
        float v2 = (lane < 8) ? sh[lane] : 0.f;
#pragma unroll
        for (int o = 4; o > 0; o >>= 1) v2 += __shfl_xor_sync(0xffffffffu, v2, o);
        if (lane == 0) sh[0] = v2;
    }
    __syncthreads();
    float r = sh[0];
    __syncthreads();
    return r;
}

template <int EMIT>
__global__ __launch_bounds__(256) void ln_kernel(const float* __restrict__ x,
                                                 float* __restrict__ y,
                                                 bf16* __restrict__ yh, bf16* __restrict__ yl,
                                                 const float* __restrict__ g,
                                                 const float* __restrict__ b) {
    int row = blockIdx.x;
    const float* xr = x + (size_t)row * C_;
    int t = threadIdx.x;
    float v0 = xr[t], v1 = xr[t + 256], v2 = xr[t + 512], v3 = xr[t + 768];
    float s = blockReduceSum(v0 + v1 + v2 + v3);
    float mean = s * (1.f / C_);
    float d0 = v0 - mean, d1 = v1 - mean, d2 = v2 - mean, d3 = v3 - mean;
    float s2 = blockReduceSum(d0 * d0 + d1 * d1 + d2 * d2 + d3 * d3);
    float inv = rsqrtf(s2 * (1.f / C_) + 1e-5f);
    size_t base = (size_t)row * C_;
    float o0 = d0 * inv * g[t]       + b[t];
    float o1 = d1 * inv * g[t + 256] + b[t + 256];
    float o2 = d2 * inv * g[t + 512] + b[t + 512];
    float o3 = d3 * inv * g[t + 768] + b[t + 768];
    y[base + t] = o0; y[base + t + 256] = o1; y[base + t + 512] = o2; y[base + t + 768] = o3;
    if (EMIT) {
        split2(o0, yh[base + t],       yl[base + t]);
        split2(o1, yh[base + t + 256], yl[base + t + 256]);
        split2(o2, yh[base + t + 512], yl[base + t + 512]);
        split2(o3, yh[base + t + 768], yl[base + t + 768]);
    }
}

// ---------------- elementwise ----------------
__global__ __launch_bounds__(256) void embed_kernel(const int* __restrict__ idx,
                                                    const float* __restrict__ emb,
                                                    float* __restrict__ X) {
    int i = blockIdx.x * 256 + threadIdx.x;
    int row = i >> 10, c = i & 1023;
    X[i] = emb[(size_t)idx[row] * C_ + c];
}

__global__ __launch_bounds__(256) void mix_kernel(const float* __restrict__ hs,
                                                  bf16* __restrict__ mh, bf16* __restrict__ ml) {
    int i = blockIdx.x * 256 + threadIdx.x;
    int row = i >> 10, t = row & (T_ - 1);
    float prev = (t == 0) ? 0.f : hs[i - C_];
    split2(0.5f * (hs[i] + prev), mh[i], ml[i]);
}

__global__ __launch_bounds__(256) void rs_kernel(const float* __restrict__ r,
                                                 const float* __restrict__ st,
                                                 bf16* __restrict__ oh, bf16* __restrict__ ol) {
    int i = blockIdx.x * 256 + threadIdx.x;
    split2(r[i] * st[i], oh[i], ol[i]);
}

// ---------------- RWKV scan ----------------
__global__ __launch_bounds__(256) void scan1_kernel(const float* __restrict__ K,
                                                    const float* __restrict__ V,
                                                    float* __restrict__ part) {
    int g = blockIdx.x * 256 + threadIdx.x;
    int c = g & (C_ - 1), ch = (g >> 10) & (NCH - 1), b = g >> 15;
    size_t base = ((size_t)(b * T_ + ch * CHL)) * C_ + c;
    float s = 0.f;
#pragma unroll 4
    for (int j = 0; j < CHL; j++) { s += K[base] * V[base]; base += C_; }
    part[g] = s;
}

__global__ __launch_bounds__(256) void scan2_kernel(float* __restrict__ part) {
    int g = blockIdx.x * 256 + threadIdx.x;
    int c = g & (C_ - 1), b = g >> 10;
    float run = 0.f;
#pragma unroll
    for (int ch = 0; ch < NCH; ch++) {
        size_t i = ((size_t)(b * NCH + ch)) * C_ + c;
        float tv = part[i]; part[i] = run; run += tv;
    }
}

__global__ __launch_bounds__(256) void scan3_kernel(const float* __restrict__ K,
                                                    const float* __restrict__ V,
                                                    const float* __restrict__ part,
                                                    float* __restrict__ st,
                                                    bf16* __restrict__ sh, bf16* __restrict__ sl) {
    int g = blockIdx.x * 256 + threadIdx.x;
    int c = g & (C_ - 1), ch = (g >> 10) & (NCH - 1), b = g >> 15;
    size_t base = ((size_t)(b * T_ + ch * CHL)) * C_ + c;
    float run = part[g];
#pragma unroll 4
    for (int j = 0; j < CHL; j++) {
        run += K[base] * V[base];
        float v = run / (float)(ch * CHL + j + 1);
        st[base] = v;
        split2(v, sh[base], sl[base]);
        base += C_;
    }
}

// ---------------- router (fp32) ----------------
__global__ __launch_bounds__(256) void route_kernel(const float* __restrict__ Hh,
                                                    const float* __restrict__ wconf,
                                                    const float* __restrict__ waff,
                                                    const float* __restrict__ shares,
                                                    int* __restrict__ win,
                                                    float* __restrict__ scale) {
    int token = blockIdx.x * 8 + (threadIdx.x >> 5);
    int lane = threadIdx.x & 31;
    const float* h = Hh + (size_t)token * C_;
    float sc0 = 0, sc1 = 0, sc2 = 0, sa0 = 0, sa1 = 0, sa2 = 0;
    for (int c = lane; c < C_; c += 32) {
        float hv = h[c];
        sc0 = fmaf(hv, wconf[c], sc0);
        sc1 = fmaf(hv, wconf[C_ + c], sc1);
        sc2 = fmaf(hv, wconf[2 * C_ + c], sc2);
        sa0 = fmaf(hv, waff[c * E_ + 0], sa0);
        sa1 = fmaf(hv, waff[c * E_ + 1], sa1);
        sa2 = fmaf(hv, waff[c * E_ + 2], sa2);
    }
#pragma unroll
    for (int o = 16; o > 0; o >>= 1) {
        sc0 += __shfl_xor_sync(0xffffffffu, sc0, o);
        sc1 += __shfl_xor_sync(0xffffffffu, sc1, o);
        sc2 += __shfl_xor_sync(0xffffffffu, sc2, o);
        sa0 += __shfl_xor_sync(0xffffffffu, sa0, o);
        sa1 += __shfl_xor_sync(0xffffffffu, sa1, o);
        sa2 += __shfl_xor_sync(0xffffffffu, sa2, o);
    }
    if (lane == 0) {
        float c0 = 1.f / (1.f + expf(-sc0));
        float c1 = 1.f / (1.f + expf(-sc1));
        float c2 = 1.f / (1.f + expf(-sc2));
        float b0 = c0 * shares[0] + sa0;
        float b1 = c1 * shares[1] + sa1;
        float b2 = c2 * shares[2] + sa2;
        int w = 0; float bb = b0, cw = c0;
        if (b1 > bb) { bb = b1; w = 1; cw = c1; }
        if (b2 > bb) { bb = b2; w = 2; cw = c2; }
        win[token] = w;
        scale[token] = cw / (cw + 1e-6f);
    }
}

// ---------------- MoE dispatch: compact / gather / scatter ----------------
__global__ void zero_cnt_kernel() {
    if (threadIdx.x < E_) g_CNT[threadIdx.x] = 0;
}

__global__ __launch_bounds__(256) void compact_kernel(const int* __restrict__ win) {
    int t = blockIdx.x * 256 + threadIdx.x;
    int w = win[t];
    int pos = atomicAdd(&g_CNT[w], 1);
    g_LIST[w][pos] = t;
}

__global__ __launch_bounds__(256) void gather_kernel(const bf16* __restrict__ sh,
                                                     const bf16* __restrict__ sl,
                                                     bf16* __restrict__ dh, bf16* __restrict__ dl,
                                                     const int* __restrict__ list,
                                                     const int* __restrict__ cnt, int Kc) {
    int row = blockIdx.x * 8 + (threadIdx.x >> 5);
    if (row >= *cnt) return;
    int lane = threadIdx.x & 31;
    int tok = list[row];
    const uint4* s0 = (const uint4*)(sh + (size_t)tok * Kc);
    const uint4* s1 = (const uint4*)(sl + (size_t)tok * Kc);
    uint4* d0 = (uint4*)(dh + (size_t)row * Kc);
    uint4* d1 = (uint4*)(dl + (size_t)row * Kc);
    int nv = Kc >> 3;
    for (int i = lane; i < nv; i += 32) { d0[i] = s0[i]; d1[i] = s1[i]; }
}

__global__ __launch_bounds__(256) void scatter_kernel(float* __restrict__ X,
                                                      const float* __restrict__ EC,
                                                      const int* __restrict__ list,
                                                      const int* __restrict__ cnt,
                                                      const float* __restrict__ scale) {
    int row = blockIdx.x * 8 + (threadIdx.x >> 5);
    if (row >= *cnt) return;
    int lane = threadIdx.x & 31;
    int tok = list[row];
    float sc = scale[tok];
    const float4* s = (const float4*)(EC + (size_t)row * C_);
    float4* d = (float4*)(X + (size_t)tok * C_);
    for (int i = lane; i < C_ / 4; i += 32) {
        float4 v = s[i]; float4 o = d[i];
        o.x += v.x * sc; o.y += v.y * sc; o.z += v.z * sc; o.w += v.w * sc;
        d[i] = o;
    }
}

// ---- weight transpose+split: in [z][K][N] f32 -> out [z][N][K] bf16 hi/lo ----
__global__ __launch_bounds__(256) void wt_kernel(const float* __restrict__ in,
                                                 bf16* __restrict__ oh, bf16* __restrict__ ol,
                                                 int K, int N) {
    __shared__ float t[32][33];
    int z = blockIdx.z;
    const float* ip = in + (size_t)z * K * N;
    int n0 = blockIdx.x * 32, k0 = blockIdx.y * 32;
    int tx = threadIdx.x, ty = threadIdx.y;
#pragma unroll
    for (int j = 0; j < 32; j += 8)
        t[ty + j][tx] = ip[(size_t)(k0 + ty + j) * N + n0 + tx];
    __syncthreads();
    size_t ob = (size_t)z * K * N;
#pragma unroll
    for (int j = 0; j < 32; j += 8) {
        size_t o = ob + (size_t)(n0 + ty + j) * K + k0 + tx;
        split2(t[tx][ty + j], oh[o], ol[o]);
    }
}

// ---------------------------------------------------------------------------
// bf16x3 tensor-core GEMM: CTA 128x128, 8 warps of 64x32, BK=32, 2-stage
// cp.async ping-pong, ldmatrix fragments, grid x = M-tiles (B reuse in L2).
// Register-dieted (transient B frags) + launch_bounds(256,2) -> 2 CTAs/SM.
// ---------------------------------------------------------------------------
enum { OP_NONE = 0, OP_SIG = 1, OP_RELU = 2, OP_ADD = 3, OP_ADDRELU = 4 };

#define PADK 40
#define PLANE_B (128 * PADK * 2)
#define SMEM_BYTES (8 * PLANE_B)

__device__ __forceinline__ uint32_t s2u(const void* p) {
    uint32_t a;
    asm("{ .reg .u64 t; cvta.to.shared.u64 t, %1; cvt.u32.u64 %0, t; }" : "=r"(a) : "l"(p));
    return a;
}
__device__ __forceinline__ void cpa16(uint32_t d, const void* s) {
    asm volatile("cp.async.cg.shared.global [%0], [%1], 16;" :: "r"(d), "l"(s));
}
__device__ __forceinline__ void ldsm4(uint32_t* r, uint32_t a) {
    asm volatile("ldmatrix.sync.aligned.m8n8.x4.shared.b16 {%0,%1,%2,%3}, [%4];"
                 : "=r"(r[0]), "=r"(r[1]), "=r"(r[2]), "=r"(r[3]) : "r"(a));
}
__device__ __forceinline__ void mma_bf16(float* c, const uint32_t* a, uint32_t b0, uint32_t b1) {
    asm volatile(
        "mma.sync.aligned.m16n8k16.row.col.f32.bf16.bf16.f32 "
        "{%0,%1,%2,%3}, {%4,%5,%6,%7}, {%8,%9}, {%0,%1,%2,%3};"
        : "+f"(c[0]), "+f"(c[1]), "+f"(c[2]), "+f"(c[3])
        : "r"(a[0]), "r"(a[1]), "r"(a[2]), "r"(a[3]), "r"(b0), "r"(b1));
}

template <int OP, int WB>
__global__ __launch_bounds__(256, 2) void hgemm_kernel(
        const bf16* __restrict__ Ahp, const bf16* __restrict__ Alp,
        const bf16* __restrict__ Bhp, const bf16* __restrict__ Blp,
        const float* __restrict__ Cin, float* __restrict__ Cout,
        bf16* __restrict__ Eh, bf16* __restrict__ El,
        const int* __restrict__ cntp,
        int M, int N, int K, int ldb) {
    const int m0 = blockIdx.x * 128, n0 = blockIdx.y * 128;
    if (cntp && m0 >= *cntp) return;
    extern __shared__ __align__(16) char smem[];
    const uint32_t uS = s2u(smem);
    const int tid = threadIdx.x, wid = tid >> 5, lane = tid & 31;
    const int nk = K >> 5;

    const int lrow = tid >> 1, lhalf = tid & 1;
    const bf16* gA[2] = { Ahp + (size_t)(m0 + lrow) * K + lhalf * 16,
                          Alp + (size_t)(m0 + lrow) * K + lhalf * 16 };
    const bf16* gB[2] = { Bhp + (size_t)(n0 + lrow) * ldb + lhalf * 16,
                          Blp + (size_t)(n0 + lrow) * ldb + lhalf * 16 };
    const uint32_t sOff = (lrow * PADK + lhalf * 16) * 2;

#define LOAD_STAGE(s, kt) do {                                            \
        size_t ko = (size_t)(kt) * 32;                                    \
        uint32_t sb = uS + (s) * 4 * PLANE_B + sOff;                      \
        cpa16(sb,                gA[0] + ko);                             \
        cpa16(sb + 16,           gA[0] + ko + 8);                         \
        cpa16(sb + PLANE_B,      gA[1] + ko);                             \
        cpa16(sb + PLANE_B + 16, gA[1] + ko + 8);                         \
        cpa16(sb + 2 * PLANE_B,      gB[0] + ko);                         \
        cpa16(sb + 2 * PLANE_B + 16, gB[0] + ko + 8);                     \
        cpa16(sb + 3 * PLANE_B,      gB[1] + ko);                         \
        cpa16(sb + 3 * PLANE_B + 16, gB[1] + ko + 8);                     \
        asm volatile("cp.async.commit_group;" ::: "memory");              \
    } while (0)

    float acc[4][4][4];
#pragma unroll
    for (int i = 0; i < 4; i++)
#pragma unroll
        for (int j = 0; j < 4; j++)
#pragma unroll
            for (int q = 0; q < 4; q++) acc[i][j][q] = 0.f;

    const int mB = (wid & 1) * 64, nB = (wid >> 1) * 32;
    const int lane16 = lane & 15, laneHi = lane >> 4;
    const uint32_t aFrag = ((mB + lane16) * PADK + laneHi * 8) * 2;
    const uint32_t bFrag = ((nB + lane16) * PADK + laneHi * 8) * 2;

    LOAD_STAGE(0, 0);

    for (int kt = 0; kt < nk; kt++) {
        const int s = kt & 1;
        asm volatile("cp.async.wait_group 0;" ::: "memory");
        __syncthreads();
        if (kt + 1 < nk) LOAD_STAGE(s ^ 1, kt + 1);

        const uint32_t pAh = uS + s * 4 * PLANE_B;
        const uint32_t pAl = pAh + PLANE_B;
        const uint32_t pBh = pAh + 2 * PLANE_B;
        const uint32_t pBl = pAh + 3 * PLANE_B;
#pragma unroll
        for (int kk = 0; kk < 2; kk++) {
            const uint32_t k0b = kk * 32;
            uint32_t ah[4][4], al[4][4];
#pragma unroll
            for (int i = 0; i < 4; i++) {
                ldsm4(ah[i], pAh + aFrag + k0b + i * (16 * PADK * 2));
                ldsm4(al[i], pAl + aFrag + k0b + i * (16 * PADK * 2));
            }
#pragma unroll
            for (int jj = 0; jj < 2; jj++) {
                uint32_t bh[4], bl[4];
                ldsm4(bh, pBh + bFrag + k0b + jj * (16 * PADK * 2));
                ldsm4(bl, pBl + bFrag + k0b + jj * (16 * PADK * 2));
#pragma unroll
                for (int t = 0; t < 2; t++) {
                    const int j = jj * 2 + t;
#pragma unroll
                    for (int i = 0; i < 4; i++) {
                        mma_bf16(acc[i][j], ah[i], bh[t], bh[2 + t]);
                        mma_bf16(acc[i][j], ah[i], bl[t], bl[2 + t]);
                        mma_bf16(acc[i][j], al[i], bh[t], bh[2 + t]);
                    }
                }
            }
        }
        __syncthreads();
    }

    const int lr = lane >> 2, lc = lane & 3;
#pragma unroll
    for (int i = 0; i < 4; i++)
#pragma unroll
        for (int j = 0; j < 4; j++)
#pragma unroll
            for (int h = 0; h < 2; h++) {
                int row = m0 + mB + i * 16 + lr + h * 8;
                int col = n0 + nB + j * 8 + lc * 2;
                float v0 = acc[i][j][h * 2 + 0];
                float v1 = acc[i][j][h * 2 + 1];
                if (OP == OP_SIG) {
                    v0 = 1.f / (1.f + expf(-v0)); v1 = 1.f / (1.f + expf(-v1));
                } else if (OP == OP_RELU) {
                    v0 = fmaxf(v0, 0.f); v1 = fmaxf(v1, 0.f);
                } else if (OP == OP_ADD) {
                    float2 o = *(const float2*)&Cin[(size_t)row * N + col];
                    v0 += o.x; v1 += o.y;
                } else if (OP == OP_ADDRELU) {
                    float2 o = *(const float2*)&Cin[(size_t)row * N + col];
                    v0 = fmaxf(v0 + o.x, 0.f); v1 = fmaxf(v1 + o.y, 0.f);
                }
                if (WB) {
                    bf16 h0, l0, h1, l1;
                    split2(v0, h0, l0); split2(v1, h1, l1);
                    size_t o = (size_t)row * N + col;
                    *(__nv_bfloat162*)&Eh[o] = __halves2bfloat162(h0, h1);
                    *(__nv_bfloat162*)&El[o] = __halves2bfloat162(l0, l1);
                } else {
                    *(float2*)&Cout[(size_t)row * N + col] = make_float2(v0, v1);
                }
            }
}

static void gemm(int op, const bf16* Ah, const bf16* Al, const bf16* Bh, const bf16* Bl,
                 const float* Cin, float* Cout, bf16* Eh, bf16* El, const int* cntp,
                 int M, int N, int K, int ldb) {
    dim3 grid(M / 128, N / 128), block(256);
    switch (op) {
        case OP_NONE:
            cudaFuncSetAttribute(hgemm_kernel<OP_NONE, 0>, cudaFuncAttributeMaxDynamicSharedMemorySize, SMEM_BYTES);
            hgemm_kernel<OP_NONE, 0><<<grid, block, SMEM_BYTES>>>(Ah, Al, Bh, Bl, Cin, Cout, Eh, El, cntp, M, N, K, ldb);
            break;
        case OP_SIG:
            cudaFuncSetAttribute(hgemm_kernel<OP_SIG, 0>, cudaFuncAttributeMaxDynamicSharedMemorySize, SMEM_BYTES);
            hgemm_kernel<OP_SIG, 0><<<grid, block, SMEM_BYTES>>>(Ah, Al, Bh, Bl, Cin, Cout, Eh, El, cntp, M, N, K, ldb);
            break;
        case OP_ADD:
            cudaFuncSetAttribute(hgemm_kernel<OP_ADD, 0>, cudaFuncAttributeMaxDynamicSharedMemorySize, SMEM_BYTES);
            hgemm_kernel<OP_ADD, 0><<<grid, block, SMEM_BYTES>>>(Ah, Al, Bh, Bl, Cin, Cout, Eh, El, cntp, M, N, K, ldb);
            break;
        case OP_RELU:
            cudaFuncSetAttribute(hgemm_kernel<OP_RELU, 1>, cudaFuncAttributeMaxDynamicSharedMemorySize, SMEM_BYTES);
            hgemm_kernel<OP_RELU, 1><<<grid, block, SMEM_BYTES>>>(Ah, Al, Bh, Bl, Cin, Cout, Eh, El, cntp, M, N, K, ldb);
            break;
        case OP_ADDRELU:
            cudaFuncSetAttribute(hgemm_kernel<OP_ADDRELU, 1>, cudaFuncAttributeMaxDynamicSharedMemorySize, SMEM_BYTES);
            hgemm_kernel<OP_ADDRELU, 1><<<grid, block, SMEM_BYTES>>>(Ah, Al, Bh, Bl, Cin, Cout, Eh, El, cntp, M, N, K, ldb);
            break;
    }
}

// ---------------- host orchestration ----------------
extern "C" void kernel_launch(void* const* d_in, const int* in_sizes, int n_in,
                              void* d_out, int out_size) {
    (void)in_sizes; (void)n_in; (void)out_size;
    const int*   idx    = (const int*)d_in[0];
    const float* shares = (const float*)d_in[1];
    const float* emb    = (const float*)d_in[2];
    const float* ln1_g  = (const float*)d_in[3];
    const float* ln1_b  = (const float*)d_in[4];
    const float* ln2_g  = (const float*)d_in[5];
    const float* ln2_b  = (const float*)d_in[6];
    const float* Wr     = (const float*)d_in[7];
    const float* Wk     = (const float*)d_in[8];
    const float* Wv     = (const float*)d_in[9];
    const float* Wo     = (const float*)d_in[10];
    const float* W1     = (const float*)d_in[11];
    const float* W2     = (const float*)d_in[12];
    const float* w_conf = (const float*)d_in[13];
    const float* Wl1    = (const float*)d_in[14];
    const float* Wl2    = (const float*)d_in[15];
    /* d_in[16] = W_diff unused */
    const float* W_aff  = (const float*)d_in[17];
    const float* lnf_g  = (const float*)d_in[18];
    const float* lnf_b  = (const float*)d_in[19];
    const float* head_W = (const float*)d_in[20];

    float *X, *HS, *R, *Kb, *Vb, *ST, *Hh, *EC, *FF, *PART, *SCL;
    int *WIN, *CNT, *LIST;
    cudaGetSymbolAddress((void**)&X, g_X);   cudaGetSymbolAddress((void**)&HS, g_HS);
    cudaGetSymbolAddress((void**)&R, g_R);   cudaGetSymbolAddress((void**)&Kb, g_Kb);
    cudaGetSymbolAddress((void**)&Vb, g_Vb); cudaGetSymbolAddress((void**)&ST, g_ST);
    cudaGetSymbolAddress((void**)&Hh, g_Hh); cudaGetSymbolAddress((void**)&EC, g_EC);
    cudaGetSymbolAddress((void**)&FF, g_FF); cudaGetSymbolAddress((void**)&PART, g_PART);
    cudaGetSymbolAddress((void**)&SCL, g_SCL); cudaGetSymbolAddress((void**)&WIN, g_WIN);
    cudaGetSymbolAddress((void**)&CNT, g_CNT); cudaGetSymbolAddress((void**)&LIST, g_LIST);
    bf16 *MIXb, *RSb, *Hb, *STb, *HSb, *FFb, *GA, *GS;
    cudaGetSymbolAddress((void**)&MIXb, g_MIXb); cudaGetSymbolAddress((void**)&RSb, g_RSb);
    cudaGetSymbolAddress((void**)&Hb, g_Hb);     cudaGetSymbolAddress((void**)&STb, g_STb);
    cudaGetSymbolAddress((void**)&HSb, g_HSb);   cudaGetSymbolAddress((void**)&FFb, g_FFb);
    cudaGetSymbolAddress((void**)&GA, g_GA);     cudaGetSymbolAddress((void**)&GS, g_GS);
    bf16 *WrT, *WkT, *WvT, *WoT, *W1T, *W2T, *Wl1T, *Wl2T, *HT;
    cudaGetSymbolAddress((void**)&WrT, g_WrT);   cudaGetSymbolAddress((void**)&WkT, g_WkT);
    cudaGetSymbolAddress((void**)&WvT, g_WvT);   cudaGetSymbolAddress((void**)&WoT, g_WoT);
    cudaGetSymbolAddress((void**)&W1T, g_W1T);   cudaGetSymbolAddress((void**)&W2T, g_W2T);
    cudaGetSymbolAddress((void**)&Wl1T, g_Wl1T); cudaGetSymbolAddress((void**)&Wl2T, g_Wl2T);
    cudaGetSymbolAddress((void**)&HT, g_HT);

    const size_t PW  = (size_t)L_ * C_ * C_;
    const size_t PW1 = (size_t)L_ * 2 * H_ * C_;
    const size_t PW2 = (size_t)L_ * 2 * C_ * H_;
    const size_t PL1 = (size_t)L_ * H_ * 2 * C_;
    const size_t PL2 = (size_t)L_ * C_ * H_;
    const size_t PHT = (size_t)V_ * C_;
    const size_t PA  = (size_t)SZ;
    const size_t PF  = (size_t)BT * H_;

    dim3 tb(32, 8);
    wt_kernel<<<dim3(C_ / 32, C_ / 32, L_), tb>>>(Wr, WrT, WrT + PW, C_, C_);
    wt_kernel<<<dim3(C_ / 32, C_ / 32, L_), tb>>>(Wk, WkT, WkT + PW, C_, C_);
    wt_kernel<<<dim3(C_ / 32, C_ / 32, L_), tb>>>(Wv, WvT, WvT + PW, C_, C_);
    wt_kernel<<<dim3(C_ / 32, C_ / 32, L_), tb>>>(Wo, WoT, WoT + PW, C_, C_);
    wt_kernel<<<dim3(H_ / 32, C_ / 32, L_ * 2), tb>>>(W1, W1T, W1T + PW1, C_, H_);
    wt_kernel<<<dim3(C_ / 32, H_ / 32, L_ * 2), tb>>>(W2, W2T, W2T + PW2, H_, C_);
    wt_kernel<<<dim3(H_ / 32, (2 * C_) / 32, L_), tb>>>(Wl1, Wl1T, Wl1T + PL1, 2 * C_, H_);
    wt_kernel<<<dim3(C_ / 32, H_ / 32, L_), tb>>>(Wl2, Wl2T, Wl2T + PL2, H_, C_);
    wt_kernel<<<dim3(V_ / 32, C_ / 32, 1), tb>>>(head_W, HT, HT + PHT, C_, V_);

    const int EW = SZ / 256;
    embed_kernel<<<EW, 256>>>(idx, emb, X);

    for (int l = 0; l < L_; l++) {
        const size_t wo = (size_t)l * C_ * C_;
        ln_kernel<0><<<BT, 256>>>(X, HS, nullptr, nullptr, ln1_g + (size_t)l * C_, ln1_b + (size_t)l * C_);
        mix_kernel<<<EW, 256>>>(HS, MIXb, MIXb + PA);
        gemm(OP_SIG,  MIXb, MIXb + PA, WrT + wo, WrT + PW + wo, nullptr, R,  nullptr, nullptr, nullptr, BT, C_, C_, C_);
        gemm(OP_NONE, MIXb, MIXb + PA, WkT + wo, WkT + PW + wo, nullptr, Kb, nullptr, nullptr, nullptr, BT, C_, C_, C_);
        gemm(OP_NONE, MIXb, MIXb + PA, WvT + wo, WvT + PW + wo, nullptr, Vb, nullptr, nullptr, nullptr, BT, C_, C_, C_);
        scan1_kernel<<<(B_ * NCH * C_) / 256, 256>>>(Kb, Vb, PART);
        scan2_kernel<<<(B_ * C_) / 256, 256>>>(PART);
        scan3_kernel<<<(B_ * NCH * C_) / 256, 256>>>(Kb, Vb, PART, ST, STb, STb + PA);
        rs_kernel<<<EW, 256>>>(R, ST, RSb, RSb + PA);
        gemm(OP_ADD, RSb, RSb + PA, WoT + wo, WoT + PW + wo, X, X, nullptr, nullptr, nullptr, BT, C_, C_, C_);
        ln_kernel<1><<<BT, 256>>>(X, Hh, Hb, Hb + PA, ln2_g + (size_t)l * C_, ln2_b + (size_t)l * C_);
        route_kernel<<<BT / 8, 256>>>(Hh, w_conf + (size_t)l * E_ * C_,
                                      W_aff + (size_t)l * C_ * E_,
                                      shares + (size_t)l * E_, WIN, SCL);
        zero_cnt_kernel<<<1, 32>>>();
        compact_kernel<<<BT / 256, 256>>>(WIN);

        for (int e = 0; e < 2; e++) {
            const int* cnt_e = CNT + e;
            const int* list_e = LIST + (size_t)e * BT;
            const size_t w1o = ((size_t)l * 2 + e) * H_ * C_;
            const size_t w2o = ((size_t)l * 2 + e) * C_ * H_;
            gather_kernel<<<BT / 8, 256>>>(Hb, Hb + PA, GA, GA + PA, list_e, cnt_e, C_);
            gemm(OP_RELU, GA, GA + PA, W1T + w1o, W1T + PW1 + w1o, nullptr, nullptr,
                 FFb, FFb + PF, cnt_e, BT, H_, C_, C_);
            gemm(OP_NONE, FFb, FFb + PF, W2T + w2o, W2T + PW2 + w2o, nullptr, EC,
                 nullptr, nullptr, cnt_e, BT, C_, H_, H_);
            scatter_kernel<<<BT / 8, 256>>>(X, EC, list_e, cnt_e, SCL);
        }

        {
            const int* cnt_e = CNT + 2;
            const int* list_e = LIST + (size_t)2 * BT;
            const size_t l1o = (size_t)l * H_ * 2 * C_;
            const size_t l2o = (size_t)l * C_ * H_;
            gather_kernel<<<BT / 8, 256>>>(Hb, Hb + PA, GA, GA + PA, list_e, cnt_e, C_);
            gather_kernel<<<BT / 8, 256>>>(STb, STb + PA, GS, GS + PA, list_e, cnt_e, C_);
            gemm(OP_NONE,    GA, GA + PA, Wl1T + l1o,      Wl1T + PL1 + l1o,      nullptr, FF,
                 nullptr, nullptr, cnt_e, BT, H_, C_, 2 * C_);
            gemm(OP_ADDRELU, GS, GS + PA, Wl1T + l1o + C_, Wl1T + PL1 + l1o + C_, FF, nullptr,
                 FFb, FFb + PF, cnt_e, BT, H_, C_, 2 * C_);
            gemm(OP_NONE, FFb, FFb + PF, Wl2T + l2o, Wl2T + PL2 + l2o, nullptr, EC,
                 nullptr, nullptr, cnt_e, BT, C_, H_, H_);
            scatter_kernel<<<BT / 8, 256>>>(X, EC, list_e, cnt_e, SCL);
        }
    }

    ln_kernel<1><<<BT, 256>>>(X, HS, HSb, HSb + PA, lnf_g, lnf_b);
    gemm(OP_NONE, HSb, HSb + PA, HT, HT + PHT, nullptr, (float*)d_out, nullptr, nullptr, nullptr, BT, V_, C_, C_);
}

// round 13
// speedup vs baseline: 1.1372x; 1.1372x over previous
#include <cuda_runtime.h>
#include <cuda_bf16.h>
#include <cstdint>
#include <math.h>

#define B_ 2
#define T_ 2048
#define BT 4096
#define C_ 1024
#define V_ 32000
#define L_ 4
#define E_ 3
#define H_ 4096
#define NCH 32
#define CHL 64
#define SZ (BT*C_)

typedef __nv_bfloat16 bf16;

// ---------------- static scratch (no allocations) ----------------
__device__ float g_X[SZ], g_HS[SZ], g_R[SZ], g_Kb[SZ], g_Vb[SZ], g_ST[SZ], g_Hh[SZ];
__device__ float g_EC[SZ];
__device__ float g_FF[(size_t)BT * H_];
__device__ float g_PART[B_ * NCH * C_], g_SCL[BT];
__device__ int   g_WIN[BT];
__device__ int   g_CNT[E_];
__device__ int   g_LIST[E_][BT];

__device__ bf16 g_MIXb[2][SZ], g_RSb[2][SZ], g_Hb[2][SZ], g_STb[2][SZ], g_HSb[2][SZ];
__device__ bf16 g_GA[2][SZ];
__device__ bf16 g_GS[2][SZ];
__device__ bf16 g_FFb[2][(size_t)BT * H_];

__device__ bf16 g_WrT[2][(size_t)L_ * C_ * C_], g_WkT[2][(size_t)L_ * C_ * C_];
__device__ bf16 g_WvT[2][(size_t)L_ * C_ * C_], g_WoT[2][(size_t)L_ * C_ * C_];
__device__ bf16 g_W1T[2][(size_t)L_ * 2 * H_ * C_], g_W2T[2][(size_t)L_ * 2 * C_ * H_];
__device__ bf16 g_Wl1T[2][(size_t)L_ * H_ * 2 * C_], g_Wl2T[2][(size_t)L_ * C_ * H_];
__device__ bf16 g_HT[2][(size_t)V_ * C_];

__device__ __forceinline__ void split2(float x, bf16& h, bf16& l) {
    h = __float2bfloat16(x);
    l = __float2bfloat16(x - __bfloat162float(h));
}

// ---------------- block reduce / LN ----------------
__device__ __forceinline__ float blockReduceSum(float val) {
    __shared__ float sh[8];
    int lane = threadIdx.x & 31, w = threadIdx.x >> 5;
#pragma unroll
    for (int o = 16; o > 0; o >>= 1) val += __shfl_xor_sync(0xffffffffu, val, o);
    if (lane == 0) sh[w] = val;
    __syncthreads();
    if (w == 0) {
        float v2 = (lane < 8) ? sh[lane] : 0.f;
#pragma unroll
        for (int o = 4; o > 0; o >>= 1) v2 += __shfl_xor_sync(0xffffffffu, v2, o);
        if (lane == 0) sh[0] = v2;
    }
    __syncthreads();
    float r = sh[0];
    __syncthreads();
    return r;
}

template <int EMIT>
__global__ __launch_bounds__(256) void ln_kernel(const float* __restrict__ x,
                                                 float* __restrict__ y,
                                                 bf16* __restrict__ yh, bf16* __restrict__ yl,
                                                 const float* __restrict__ g,
                                                 const float* __restrict__ b) {
    int row = blockIdx.x;
    const float* xr = x + (size_t)row * C_;
    int t = threadIdx.x;
    float v0 = xr[t], v1 = xr[t + 256], v2 = xr[t + 512], v3 = xr[t + 768];
    float s = blockReduceSum(v0 + v1 + v2 + v3);
    float mean = s * (1.f / C_);
    float d0 = v0 - mean, d1 = v1 - mean, d2 = v2 - mean, d3 = v3 - mean;
    float s2 = blockReduceSum(d0 * d0 + d1 * d1 + d2 * d2 + d3 * d3);
    float inv = rsqrtf(s2 * (1.f / C_) + 1e-5f);
    size_t base = (size_t)row * C_;
    float o0 = d0 * inv * g[t]       + b[t];
    float o1 = d1 * inv * g[t + 256] + b[t + 256];
    float o2 = d2 * inv * g[t + 512] + b[t + 512];
    float o3 = d3 * inv * g[t + 768] + b[t + 768];
    y[base + t] = o0; y[base + t + 256] = o1; y[base + t + 512] = o2; y[base + t + 768] = o3;
    if (EMIT) {
        split2(o0, yh[base + t],       yl[base + t]);
        split2(o1, yh[base + t + 256], yl[base + t + 256]);
        split2(o2, yh[base + t + 512], yl[base + t + 512]);
        split2(o3, yh[base + t + 768], yl[base + t + 768]);
    }
}

// ---------------- elementwise ----------------
__global__ __launch_bounds__(256) void embed_kernel(const int* __restrict__ idx,
                                                    const float* __restrict__ emb,
                                                    float* __restrict__ X) {
    int i = blockIdx.x * 256 + threadIdx.x;
    int row = i >> 10, c = i & 1023;
    X[i] = emb[(size_t)idx[row] * C_ + c];
}

__global__ __launch_bounds__(256) void mix_kernel(const float* __restrict__ hs,
                                                  bf16* __restrict__ mh, bf16* __restrict__ ml) {
    int i = blockIdx.x * 256 + threadIdx.x;
    int row = i >> 10, t = row & (T_ - 1);
    float prev = (t == 0) ? 0.f : hs[i - C_];
    split2(0.5f * (hs[i] + prev), mh[i], ml[i]);
}

__global__ __launch_bounds__(256) void rs_kernel(const float* __restrict__ r,
                                                 const float* __restrict__ st,
                                                 bf16* __restrict__ oh, bf16* __restrict__ ol) {
    int i = blockIdx.x * 256 + threadIdx.x;
    split2(r[i] * st[i], oh[i], ol[i]);
}

// ---------------- RWKV scan ----------------
__global__ __launch_bounds__(256) void scan1_kernel(const float* __restrict__ K,
                                                    const float* __restrict__ V,
                                                    float* __restrict__ part) {
    int g = blockIdx.x * 256 + threadIdx.x;
    int c = g & (C_ - 1), ch = (g >> 10) & (NCH - 1), b = g >> 15;
    size_t base = ((size_t)(b * T_ + ch * CHL)) * C_ + c;
    float s = 0.f;
#pragma unroll 4
    for (int j = 0; j < CHL; j++) { s += K[base] * V[base]; base += C_; }
    part[g] = s;
}

__global__ __launch_bounds__(256) void scan2_kernel(float* __restrict__ part) {
    int g = blockIdx.x * 256 + threadIdx.x;
    int c = g & (C_ - 1), b = g >> 10;
    float run = 0.f;
#pragma unroll
    for (int ch = 0; ch < NCH; ch++) {
        size_t i = ((size_t)(b * NCH + ch)) * C_ + c;
        float tv = part[i]; part[i] = run; run += tv;
    }
}

__global__ __launch_bounds__(256) void scan3_kernel(const float* __restrict__ K,
                                                    const float* __restrict__ V,
                                                    const float* __restrict__ part,
                                                    float* __restrict__ st,
                                                    bf16* __restrict__ sh, bf16* __restrict__ sl) {
    int g = blockIdx.x * 256 + threadIdx.x;
    int c = g & (C_ - 1), ch = (g >> 10) & (NCH - 1), b = g >> 15;
    size_t base = ((size_t)(b * T_ + ch * CHL)) * C_ + c;
    float run = part[g];
#pragma unroll 4
    for (int j = 0; j < CHL; j++) {
        run += K[base] * V[base];
        float v = run / (float)(ch * CHL + j + 1);
        st[base] = v;
        split2(v, sh[base], sl[base]);
        base += C_;
    }
}

// ---------------- router (fp32) ----------------
__global__ __launch_bounds__(256) void route_kernel(const float* __restrict__ Hh,
                                                    const float* __restrict__ wconf,
                                                    const float* __restrict__ waff,
                                                    const float* __restrict__ shares,
                                                    int* __restrict__ win,
                                                    float* __restrict__ scale) {
    int token = blockIdx.x * 8 + (threadIdx.x >> 5);
    int lane = threadIdx.x & 31;
    const float* h = Hh + (size_t)token * C_;
    float sc0 = 0, sc1 = 0, sc2 = 0, sa0 = 0, sa1 = 0, sa2 = 0;
    for (int c = lane; c < C_; c += 32) {
        float hv = h[c];
        sc0 = fmaf(hv, wconf[c], sc0);
        sc1 = fmaf(hv, wconf[C_ + c], sc1);
        sc2 = fmaf(hv, wconf[2 * C_ + c], sc2);
        sa0 = fmaf(hv, waff[c * E_ + 0], sa0);
        sa1 = fmaf(hv, waff[c * E_ + 1], sa1);
        sa2 = fmaf(hv, waff[c * E_ + 2], sa2);
    }
#pragma unroll
    for (int o = 16; o > 0; o >>= 1) {
        sc0 += __shfl_xor_sync(0xffffffffu, sc0, o);
        sc1 += __shfl_xor_sync(0xffffffffu, sc1, o);
        sc2 += __shfl_xor_sync(0xffffffffu, sc2, o);
        sa0 += __shfl_xor_sync(0xffffffffu, sa0, o);
        sa1 += __shfl_xor_sync(0xffffffffu, sa1, o);
        sa2 += __shfl_xor_sync(0xffffffffu, sa2, o);
    }
    if (lane == 0) {
        float c0 = 1.f / (1.f + expf(-sc0));
        float c1 = 1.f / (1.f + expf(-sc1));
        float c2 = 1.f / (1.f + expf(-sc2));
        float b0 = c0 * shares[0] + sa0;
        float b1 = c1 * shares[1] + sa1;
        float b2 = c2 * shares[2] + sa2;
        int w = 0; float bb = b0, cw = c0;
        if (b1 > bb) { bb = b1; w = 1; cw = c1; }
        if (b2 > bb) { bb = b2; w = 2; cw = c2; }
        win[token] = w;
        scale[token] = cw / (cw + 1e-6f);
    }
}

// ---------------- MoE dispatch: compact / gather / scatter ----------------
__global__ void zero_cnt_kernel() {
    if (threadIdx.x < E_) g_CNT[threadIdx.x] = 0;
}

__global__ __launch_bounds__(256) void compact_kernel(const int* __restrict__ win) {
    int t = blockIdx.x * 256 + threadIdx.x;
    int w = win[t];
    int pos = atomicAdd(&g_CNT[w], 1);
    g_LIST[w][pos] = t;
}

__global__ __launch_bounds__(256) void gather_kernel(const bf16* __restrict__ sh,
                                                     const bf16* __restrict__ sl,
                                                     bf16* __restrict__ dh, bf16* __restrict__ dl,
                                                     const int* __restrict__ list,
                                                     const int* __restrict__ cnt, int Kc) {
    int row = blockIdx.x * 8 + (threadIdx.x >> 5);
    if (row >= *cnt) return;
    int lane = threadIdx.x & 31;
    int tok = list[row];
    const uint4* s0 = (const uint4*)(sh + (size_t)tok * Kc);
    const uint4* s1 = (const uint4*)(sl + (size_t)tok * Kc);
    uint4* d0 = (uint4*)(dh + (size_t)row * Kc);
    uint4* d1 = (uint4*)(dl + (size_t)row * Kc);
    int nv = Kc >> 3;
    for (int i = lane; i < nv; i += 32) { d0[i] = s0[i]; d1[i] = s1[i]; }
}

__global__ __launch_bounds__(256) void scatter_kernel(float* __restrict__ X,
                                                      const float* __restrict__ EC,
                                                      const int* __restrict__ list,
                                                      const int* __restrict__ cnt,
                                                      const float* __restrict__ scale) {
    int row = blockIdx.x * 8 + (threadIdx.x >> 5);
    if (row >= *cnt) return;
    int lane = threadIdx.x & 31;
    int tok = list[row];
    float sc = scale[tok];
    const float4* s = (const float4*)(EC + (size_t)row * C_);
    float4* d = (float4*)(X + (size_t)tok * C_);
    for (int i = lane; i < C_ / 4; i += 32) {
        float4 v = s[i]; float4 o = d[i];
        o.x += v.x * sc; o.y += v.y * sc; o.z += v.z * sc; o.w += v.w * sc;
        d[i] = o;
    }
}

// ---- weight transpose+split: in [z][K][N] f32 -> out [z][N][K] bf16 hi/lo ----
__global__ __launch_bounds__(256) void wt_kernel(const float* __restrict__ in,
                                                 bf16* __restrict__ oh, bf16* __restrict__ ol,
                                                 int K, int N) {
    __shared__ float t[32][33];
    int z = blockIdx.z;
    const float* ip = in + (size_t)z * K * N;
    int n0 = blockIdx.x * 32, k0 = blockIdx.y * 32;
    int tx = threadIdx.x, ty = threadIdx.y;
#pragma unroll
    for (int j = 0; j < 32; j += 8)
        t[ty + j][tx] = ip[(size_t)(k0 + ty + j) * N + n0 + tx];
    __syncthreads();
    size_t ob = (size_t)z * K * N;
#pragma unroll
    for (int j = 0; j < 32; j += 8) {
        size_t o = ob + (size_t)(n0 + ty + j) * K + k0 + tx;
        split2(t[tx][ty + j], oh[o], ol[o]);
    }
}

// ---------------------------------------------------------------------------
// bf16x3 tensor-core GEMM: CTA 128x128, 8 warps of 64x32, BK=32,
// 3-stage cp.async pipeline (wait_group 1), ldmatrix fragments,
// grid x = M-tiles (head-GEMM B reuse in L2). Round-10 register profile.
// ---------------------------------------------------------------------------
enum { OP_NONE = 0, OP_SIG = 1, OP_RELU = 2, OP_ADD = 3, OP_ADDRELU = 4 };

#define PADK 40
#define PLANE_B (128 * PADK * 2)      // 10240 B
#define STAGE_TOT (4 * PLANE_B)       // 40960 B (Ah, Al, Bh, Bl)
#define SMEM_BYTES (3 * STAGE_TOT)    // 122880 B

__device__ __forceinline__ uint32_t s2u(const void* p) {
    uint32_t a;
    asm("{ .reg .u64 t; cvta.to.shared.u64 t, %1; cvt.u32.u64 %0, t; }" : "=r"(a) : "l"(p));
    return a;
}
__device__ __forceinline__ void cpa16(uint32_t d, const void* s) {
    asm volatile("cp.async.cg.shared.global [%0], [%1], 16;" :: "r"(d), "l"(s));
}
__device__ __forceinline__ void ldsm4(uint32_t* r, uint32_t a) {
    asm volatile("ldmatrix.sync.aligned.m8n8.x4.shared.b16 {%0,%1,%2,%3}, [%4];"
                 : "=r"(r[0]), "=r"(r[1]), "=r"(r[2]), "=r"(r[3]) : "r"(a));
}
__device__ __forceinline__ void mma_bf16(float* c, const uint32_t* a, uint32_t b0, uint32_t b1) {
    asm volatile(
        "mma.sync.aligned.m16n8k16.row.col.f32.bf16.bf16.f32 "
        "{%0,%1,%2,%3}, {%4,%5,%6,%7}, {%8,%9}, {%0,%1,%2,%3};"
        : "+f"(c[0]), "+f"(c[1]), "+f"(c[2]), "+f"(c[3])
        : "r"(a[0]), "r"(a[1]), "r"(a[2]), "r"(a[3]), "r"(b0), "r"(b1));
}

template <int OP, int WB>
__global__ __launch_bounds__(256) void hgemm_kernel(
        const bf16* __restrict__ Ahp, const bf16* __restrict__ Alp,
        const bf16* __restrict__ Bhp, const bf16* __restrict__ Blp,
        const float* __restrict__ Cin, float* __restrict__ Cout,
        bf16* __restrict__ Eh, bf16* __restrict__ El,
        const int* __restrict__ cntp,
        int M, int N, int K, int ldb) {
    const int m0 = blockIdx.x * 128, n0 = blockIdx.y * 128;
    if (cntp && m0 >= *cntp) return;
    extern __shared__ __align__(16) char smem[];
    const uint32_t uS = s2u(smem);
    const int tid = threadIdx.x, wid = tid >> 5, lane = tid & 31;
    const int nk = K >> 5;

    const int lrow = tid >> 1, lhalf = tid & 1;
    const bf16* gA[2] = { Ahp + (size_t)(m0 + lrow) * K + lhalf * 16,
                          Alp + (size_t)(m0 + lrow) * K + lhalf * 16 };
    const bf16* gB[2] = { Bhp + (size_t)(n0 + lrow) * ldb + lhalf * 16,
                          Blp + (size_t)(n0 + lrow) * ldb + lhalf * 16 };
    const uint32_t sOff = (lrow * PADK + lhalf * 16) * 2;

#define LOAD_STAGE(s, kt) do {                                            \
        size_t ko = (size_t)(kt) * 32;                                    \
        uint32_t sb = uS + (s) * STAGE_TOT + sOff;                        \
        cpa16(sb,                gA[0] + ko);                             \
        cpa16(sb + 16,           gA[0] + ko + 8);                         \
        cpa16(sb + PLANE_B,      gA[1] + ko);                             \
        cpa16(sb + PLANE_B + 16, gA[1] + ko + 8);                         \
        cpa16(sb + 2 * PLANE_B,      gB[0] + ko);                         \
        cpa16(sb + 2 * PLANE_B + 16, gB[0] + ko + 8);                     \
        cpa16(sb + 3 * PLANE_B,      gB[1] + ko);                         \
        cpa16(sb + 3 * PLANE_B + 16, gB[1] + ko + 8);                     \
        asm volatile("cp.async.commit_group;" ::: "memory");              \
    } while (0)

    float acc[4][4][4];
#pragma unroll
    for (int i = 0; i < 4; i++)
#pragma unroll
        for (int j = 0; j < 4; j++)
#pragma unroll
            for (int q = 0; q < 4; q++) acc[i][j][q] = 0.f;

    const int mB = (wid & 1) * 64, nB = (wid >> 1) * 32;
    const int lane16 = lane & 15, laneHi = lane >> 4;
    const uint32_t aFrag = ((mB + lane16) * PADK + laneHi * 8) * 2;
    const uint32_t bFrag = ((nB + lane16) * PADK + laneHi * 8) * 2;

    LOAD_STAGE(0, 0);
    if (nk > 1) LOAD_STAGE(1, 1);

    for (int kt = 0; kt < nk; kt++) {
        if (kt + 1 < nk) asm volatile("cp.async.wait_group 1;" ::: "memory");
        else             asm volatile("cp.async.wait_group 0;" ::: "memory");
        __syncthreads();
        if (kt + 2 < nk) LOAD_STAGE((kt + 2) % 3, kt + 2);

        const uint32_t pS = uS + (kt % 3) * STAGE_TOT;
        const uint32_t pAh = pS;
        const uint32_t pAl = pS + PLANE_B;
        const uint32_t pBh = pS + 2 * PLANE_B;
        const uint32_t pBl = pS + 3 * PLANE_B;
#pragma unroll
        for (int kk = 0; kk < 2; kk++) {
            const uint32_t k0b = kk * 32;
            uint32_t ah[4][4], al[4][4], bh[2][4], bl[2][4];
#pragma unroll
            for (int i = 0; i < 4; i++) {
                ldsm4(ah[i], pAh + aFrag + k0b + i * (16 * PADK * 2));
                ldsm4(al[i], pAl + aFrag + k0b + i * (16 * PADK * 2));
            }
#pragma unroll
            for (int jj = 0; jj < 2; jj++) {
                ldsm4(bh[jj], pBh + bFrag + k0b + jj * (16 * PADK * 2));
                ldsm4(bl[jj], pBl + bFrag + k0b + jj * (16 * PADK * 2));
            }
#pragma unroll
            for (int j = 0; j < 4; j++) {
                const int jj = j >> 1, t = j & 1;
                const uint32_t bh0 = bh[jj][t], bh1 = bh[jj][2 + t];
                const uint32_t bl0 = bl[jj][t], bl1 = bl[jj][2 + t];
#pragma unroll
                for (int i = 0; i < 4; i++) {
                    mma_bf16(acc[i][j], ah[i], bh0, bh1);
                    mma_bf16(acc[i][j], ah[i], bl0, bl1);
                    mma_bf16(acc[i][j], al[i], bh0, bh1);
                }
            }
        }
    }

    const int lr = lane >> 2, lc = lane & 3;
#pragma unroll
    for (int i = 0; i < 4; i++)
#pragma unroll
        for (int j = 0; j < 4; j++)
#pragma unroll
            for (int h = 0; h < 2; h++) {
                int row = m0 + mB + i * 16 + lr + h * 8;
                int col = n0 + nB + j * 8 + lc * 2;
                float v0 = acc[i][j][h * 2 + 0];
                float v1 = acc[i][j][h * 2 + 1];
                if (OP == OP_SIG) {
                    v0 = 1.f / (1.f + expf(-v0)); v1 = 1.f / (1.f + expf(-v1));
                } else if (OP == OP_RELU) {
                    v0 = fmaxf(v0, 0.f); v1 = fmaxf(v1, 0.f);
                } else if (OP == OP_ADD) {
                    float2 o = *(const float2*)&Cin[(size_t)row * N + col];
                    v0 += o.x; v1 += o.y;
                } else if (OP == OP_ADDRELU) {
                    float2 o = *(const float2*)&Cin[(size_t)row * N + col];
                    v0 = fmaxf(v0 + o.x, 0.f); v1 = fmaxf(v1 + o.y, 0.f);
                }
                if (WB) {
                    bf16 h0, l0, h1, l1;
                    split2(v0, h0, l0); split2(v1, h1, l1);
                    size_t o = (size_t)row * N + col;
                    *(__nv_bfloat162*)&Eh[o] = __halves2bfloat162(h0, h1);
                    *(__nv_bfloat162*)&El[o] = __halves2bfloat162(l0, l1);
                } else {
                    *(float2*)&Cout[(size_t)row * N + col] = make_float2(v0, v1);
                }
            }
}

static void gemm(int op, const bf16* Ah, const bf16* Al, const bf16* Bh, const bf16* Bl,
                 const float* Cin, float* Cout, bf16* Eh, bf16* El, const int* cntp,
                 int M, int N, int K, int ldb) {
    dim3 grid(M / 128, N / 128), block(256);
    switch (op) {
        case OP_NONE:
            cudaFuncSetAttribute(hgemm_kernel<OP_NONE, 0>, cudaFuncAttributeMaxDynamicSharedMemorySize, SMEM_BYTES);
            hgemm_kernel<OP_NONE, 0><<<grid, block, SMEM_BYTES>>>(Ah, Al, Bh, Bl, Cin, Cout, Eh, El, cntp, M, N, K, ldb);
            break;
        case OP_SIG:
            cudaFuncSetAttribute(hgemm_kernel<OP_SIG, 0>, cudaFuncAttributeMaxDynamicSharedMemorySize, SMEM_BYTES);
            hgemm_kernel<OP_SIG, 0><<<grid, block, SMEM_BYTES>>>(Ah, Al, Bh, Bl, Cin, Cout, Eh, El, cntp, M, N, K, ldb);
            break;
        case OP_ADD:
            cudaFuncSetAttribute(hgemm_kernel<OP_ADD, 0>, cudaFuncAttributeMaxDynamicSharedMemorySize, SMEM_BYTES);
            hgemm_kernel<OP_ADD, 0><<<grid, block, SMEM_BYTES>>>(Ah, Al, Bh, Bl, Cin, Cout, Eh, El, cntp, M, N, K, ldb);
            break;
        case OP_RELU:
            cudaFuncSetAttribute(hgemm_kernel<OP_RELU, 1>, cudaFuncAttributeMaxDynamicSharedMemorySize, SMEM_BYTES);
            hgemm_kernel<OP_RELU, 1><<<grid, block, SMEM_BYTES>>>(Ah, Al, Bh, Bl, Cin, Cout, Eh, El, cntp, M, N, K, ldb);
            break;
        case OP_ADDRELU:
            cudaFuncSetAttribute(hgemm_kernel<OP_ADDRELU, 1>, cudaFuncAttributeMaxDynamicSharedMemorySize, SMEM_BYTES);
            hgemm_kernel<OP_ADDRELU, 1><<<grid, block, SMEM_BYTES>>>(Ah, Al, Bh, Bl, Cin, Cout, Eh, El, cntp, M, N, K, ldb);
            break;
    }
}

// ---------------- host orchestration ----------------
extern "C" void kernel_launch(void* const* d_in, const int* in_sizes, int n_in,
                              void* d_out, int out_size) {
    (void)in_sizes; (void)n_in; (void)out_size;
    const int*   idx    = (const int*)d_in[0];
    const float* shares = (const float*)d_in[1];
    const float* emb    = (const float*)d_in[2];
    const float* ln1_g  = (const float*)d_in[3];
    const float* ln1_b  = (const float*)d_in[4];
    const float* ln2_g  = (const float*)d_in[5];
    const float* ln2_b  = (const float*)d_in[6];
    const float* Wr     = (const float*)d_in[7];
    const float* Wk     = (const float*)d_in[8];
    const float* Wv     = (const float*)d_in[9];
    const float* Wo     = (const float*)d_in[10];
    const float* W1     = (const float*)d_in[11];
    const float* W2     = (const float*)d_in[12];
    const float* w_conf = (const float*)d_in[13];
    const float* Wl1    = (const float*)d_in[14];
    const float* Wl2    = (const float*)d_in[15];
    /* d_in[16] = W_diff unused */
    const float* W_aff  = (const float*)d_in[17];
    const float* lnf_g  = (const float*)d_in[18];
    const float* lnf_b  = (const float*)d_in[19];
    const float* head_W = (const float*)d_in[20];

    float *X, *HS, *R, *Kb, *Vb, *ST, *Hh, *EC, *FF, *PART, *SCL;
    int *WIN, *CNT, *LIST;
    cudaGetSymbolAddress((void**)&X, g_X);   cudaGetSymbolAddress((void**)&HS, g_HS);
    cudaGetSymbolAddress((void**)&R, g_R);   cudaGetSymbolAddress((void**)&Kb, g_Kb);
    cudaGetSymbolAddress((void**)&Vb, g_Vb); cudaGetSymbolAddress((void**)&ST, g_ST);
    cudaGetSymbolAddress((void**)&Hh, g_Hh); cudaGetSymbolAddress((void**)&EC, g_EC);
    cudaGetSymbolAddress((void**)&FF, g_FF); cudaGetSymbolAddress((void**)&PART, g_PART);
    cudaGetSymbolAddress((void**)&SCL, g_SCL); cudaGetSymbolAddress((void**)&WIN, g_WIN);
    cudaGetSymbolAddress((void**)&CNT, g_CNT); cudaGetSymbolAddress((void**)&LIST, g_LIST);
    bf16 *MIXb, *RSb, *Hb, *STb, *HSb, *FFb, *GA, *GS;
    cudaGetSymbolAddress((void**)&MIXb, g_MIXb); cudaGetSymbolAddress((void**)&RSb, g_RSb);
    cudaGetSymbolAddress((void**)&Hb, g_Hb);     cudaGetSymbolAddress((void**)&STb, g_STb);
    cudaGetSymbolAddress((void**)&HSb, g_HSb);   cudaGetSymbolAddress((void**)&FFb, g_FFb);
    cudaGetSymbolAddress((void**)&GA, g_GA);     cudaGetSymbolAddress((void**)&GS, g_GS);
    bf16 *WrT, *WkT, *WvT, *WoT, *W1T, *W2T, *Wl1T, *Wl2T, *HT;
    cudaGetSymbolAddress((void**)&WrT, g_WrT);   cudaGetSymbolAddress((void**)&WkT, g_WkT);
    cudaGetSymbolAddress((void**)&WvT, g_WvT);   cudaGetSymbolAddress((void**)&WoT, g_WoT);
    cudaGetSymbolAddress((void**)&W1T, g_W1T);   cudaGetSymbolAddress((void**)&W2T, g_W2T);
    cudaGetSymbolAddress((void**)&Wl1T, g_Wl1T); cudaGetSymbolAddress((void**)&Wl2T, g_Wl2T);
    cudaGetSymbolAddress((void**)&HT, g_HT);

    const size_t PW  = (size_t)L_ * C_ * C_;
    const size_t PW1 = (size_t)L_ * 2 * H_ * C_;
    const size_t PW2 = (size_t)L_ * 2 * C_ * H_;
    const size_t PL1 = (size_t)L_ * H_ * 2 * C_;
    const size_t PL2 = (size_t)L_ * C_ * H_;
    const size_t PHT = (size_t)V_ * C_;
    const size_t PA  = (size_t)SZ;
    const size_t PF  = (size_t)BT * H_;

    dim3 tb(32, 8);
    wt_kernel<<<dim3(C_ / 32, C_ / 32, L_), tb>>>(Wr, WrT, WrT + PW, C_, C_);
    wt_kernel<<<dim3(C_ / 32, C_ / 32, L_), tb>>>(Wk, WkT, WkT + PW, C_, C_);
    wt_kernel<<<dim3(C_ / 32, C_ / 32, L_), tb>>>(Wv, WvT, WvT + PW, C_, C_);
    wt_kernel<<<dim3(C_ / 32, C_ / 32, L_), tb>>>(Wo, WoT, WoT + PW, C_, C_);
    wt_kernel<<<dim3(H_ / 32, C_ / 32, L_ * 2), tb>>>(W1, W1T, W1T + PW1, C_, H_);
    wt_kernel<<<dim3(C_ / 32, H_ / 32, L_ * 2), tb>>>(W2, W2T, W2T + PW2, H_, C_);
    wt_kernel<<<dim3(H_ / 32, (2 * C_) / 32, L_), tb>>>(Wl1, Wl1T, Wl1T + PL1, 2 * C_, H_);
    wt_kernel<<<dim3(C_ / 32, H_ / 32, L_), tb>>>(Wl2, Wl2T, Wl2T + PL2, H_, C_);
    wt_kernel<<<dim3(V_ / 32, C_ / 32, 1), tb>>>(head_W, HT, HT + PHT, C_, V_);

    const int EW = SZ / 256;
    embed_kernel<<<EW, 256>>>(idx, emb, X);

    for (int l = 0; l < L_; l++) {
        const size_t wo = (size_t)l * C_ * C_;
        ln_kernel<0><<<BT, 256>>>(X, HS, nullptr, nullptr, ln1_g + (size_t)l * C_, ln1_b + (size_t)l * C_);
        mix_kernel<<<EW, 256>>>(HS, MIXb, MIXb + PA);
        gemm(OP_SIG,  MIXb, MIXb + PA, WrT + wo, WrT + PW + wo, nullptr, R,  nullptr, nullptr, nullptr, BT, C_, C_, C_);
        gemm(OP_NONE, MIXb, MIXb + PA, WkT + wo, WkT + PW + wo, nullptr, Kb, nullptr, nullptr, nullptr, BT, C_, C_, C_);
        gemm(OP_NONE, MIXb, MIXb + PA, WvT + wo, WvT + PW + wo, nullptr, Vb, nullptr, nullptr, nullptr, BT, C_, C_, C_);
        scan1_kernel<<<(B_ * NCH * C_) / 256, 256>>>(Kb, Vb, PART);
        scan2_kernel<<<(B_ * C_) / 256, 256>>>(PART);
        scan3_kernel<<<(B_ * NCH * C_) / 256, 256>>>(Kb, Vb, PART, ST, STb, STb + PA);
        rs_kernel<<<EW, 256>>>(R, ST, RSb, RSb + PA);
        gemm(OP_ADD, RSb, RSb + PA, WoT + wo, WoT + PW + wo, X, X, nullptr, nullptr, nullptr, BT, C_, C_, C_);
        ln_kernel<1><<<BT, 256>>>(X, Hh, Hb, Hb + PA, ln2_g + (size_t)l * C_, ln2_b + (size_t)l * C_);
        route_kernel<<<BT / 8, 256>>>(Hh, w_conf + (size_t)l * E_ * C_,
                                      W_aff + (size_t)l * C_ * E_,
                                      shares + (size_t)l * E_, WIN, SCL);
        zero_cnt_kernel<<<1, 32>>>();
        compact_kernel<<<BT / 256, 256>>>(WIN);

        for (int e = 0; e < 2; e++) {
            const int* cnt_e = CNT + e;
            const int* list_e = LIST + (size_t)e * BT;
            const size_t w1o = ((size_t)l * 2 + e) * H_ * C_;
            const size_t w2o = ((size_t)l * 2 + e) * C_ * H_;
            gather_kernel<<<BT / 8, 256>>>(Hb, Hb + PA, GA, GA + PA, list_e, cnt_e, C_);
            gemm(OP_RELU, GA, GA + PA, W1T + w1o, W1T + PW1 + w1o, nullptr, nullptr,
                 FFb, FFb + PF, cnt_e, BT, H_, C_, C_);
            gemm(OP_NONE, FFb, FFb + PF, W2T + w2o, W2T + PW2 + w2o, nullptr, EC,
                 nullptr, nullptr, cnt_e, BT, C_, H_, H_);
            scatter_kernel<<<BT / 8, 256>>>(X, EC, list_e, cnt_e, SCL);
        }

        {
            const int* cnt_e = CNT + 2;
            const int* list_e = LIST + (size_t)2 * BT;
            const size_t l1o = (size_t)l * H_ * 2 * C_;
            const size_t l2o = (size_t)l * C_ * H_;
            gather_kernel<<<BT / 8, 256>>>(Hb, Hb + PA, GA, GA + PA, list_e, cnt_e, C_);
            gather_kernel<<<BT / 8, 256>>>(STb, STb + PA, GS, GS + PA, list_e, cnt_e, C_);
            gemm(OP_NONE,    GA, GA + PA, Wl1T + l1o,      Wl1T + PL1 + l1o,      nullptr, FF,
                 nullptr, nullptr, cnt_e, BT, H_, C_, 2 * C_);
            gemm(OP_ADDRELU, GS, GS + PA, Wl1T + l1o + C_, Wl1T + PL1 + l1o + C_, FF, nullptr,
                 FFb, FFb + PF, cnt_e, BT, H_, C_, 2 * C_);
            gemm(OP_NONE, FFb, FFb + PF, Wl2T + l2o, Wl2T + PL2 + l2o, nullptr, EC,
                 nullptr, nullptr, cnt_e, BT, C_, H_, H_);
            scatter_kernel<<<BT / 8, 256>>>(X, EC, list_e, cnt_e, SCL);
        }
    }

    ln_kernel<1><<<BT, 256>>>(X, HS, HSb, HSb + PA, lnf_g, lnf_b);
    gemm(OP_NONE, HSb, HSb + PA, HT, HT + PHT, nullptr, (float*)d_out, nullptr, nullptr, nullptr, BT, V_, C_, C_);
}

// round 14
// speedup vs baseline: 1.2305x; 1.0820x over previous
#include <cuda_runtime.h>
#include <cuda_bf16.h>
#include <cstdint>
#include <math.h>

#define B_ 2
#define T_ 2048
#define BT 4096
#define C_ 1024
#define QW 3072
#define V_ 32000
#define L_ 4
#define E_ 3
#define H_ 4096
#define NCH 32
#define CHL 64
#define SZ (BT*C_)

typedef __nv_bfloat16 bf16;

// ---------------- static scratch (no allocations) ----------------
__device__ float g_X[SZ], g_HS[SZ], g_ST[SZ], g_Hh[SZ];
__device__ float g_QKV[(size_t)BT * QW];
__device__ float g_EC[SZ];
__device__ float g_PART[B_ * NCH * C_], g_SCL[BT];
__device__ int   g_WIN[BT];
__device__ int   g_CNT[E_];
__device__ int   g_LIST[E_][BT];

__device__ bf16 g_MIXb[2][SZ], g_RSb[2][SZ], g_Hb[2][SZ], g_STb[2][SZ], g_HSb[2][SZ];
__device__ bf16 g_GA[2][SZ];
__device__ bf16 g_GA2[2][(size_t)BT * 2 * C_];
__device__ bf16 g_FFb[2][(size_t)BT * H_];

__device__ bf16 g_Wqkv[2][(size_t)L_ * QW * C_];
__device__ bf16 g_WoT[2][(size_t)L_ * C_ * C_];
__device__ bf16 g_W1T[2][(size_t)L_ * 2 * H_ * C_], g_W2T[2][(size_t)L_ * 2 * C_ * H_];
__device__ bf16 g_Wl1T[2][(size_t)L_ * H_ * 2 * C_], g_Wl2T[2][(size_t)L_ * C_ * H_];
__device__ bf16 g_HT[2][(size_t)V_ * C_];

__device__ __forceinline__ void split2(float x, bf16& h, bf16& l) {
    h = __float2bfloat16(x);
    l = __float2bfloat16(x - __bfloat162float(h));
}

// ---------------- block reduce / LN ----------------
__device__ __forceinline__ float blockReduceSum(float val) {
    __shared__ float sh[8];
    int lane = threadIdx.x & 31, w = threadIdx.x >> 5;
#pragma unroll
    for (int o = 16; o > 0; o >>= 1) val += __shfl_xor_sync(0xffffffffu, val, o);
    if (lane == 0) sh[w] = val;
    __syncthreads();
    if (w == 0) {
        float v2 = (lane < 8) ? sh[lane] : 0.f;
#pragma unroll
        for (int o = 4; o > 0; o >>= 1) v2 += __shfl_xor_sync(0xffffffffu, v2, o);
        if (lane == 0) sh[0] = v2;
    }
    __syncthreads();
    float r = sh[0];
    __syncthreads();
    return r;
}

template <int EMIT>
__global__ __launch_bounds__(256) void ln_kernel(const float* __restrict__ x,
                                                 float* __restrict__ y,
                                                 bf16* __restrict__ yh, bf16* __restrict__ yl,
                                                 const float* __restrict__ g,
                                                 const float* __restrict__ b) {
    int row = blockIdx.x;
    const float* xr = x + (size_t)row * C_;
    int t = threadIdx.x;
    float v0 = xr[t], v1 = xr[t + 256], v2 = xr[t + 512], v3 = xr[t + 768];
    float s = blockReduceSum(v0 + v1 + v2 + v3);
    float mean = s * (1.f / C_);
    float d0 = v0 - mean, d1 = v1 - mean, d2 = v2 - mean, d3 = v3 - mean;
    float s2 = blockReduceSum(d0 * d0 + d1 * d1 + d2 * d2 + d3 * d3);
    float inv = rsqrtf(s2 * (1.f / C_) + 1e-5f);
    size_t base = (size_t)row * C_;
    float o0 = d0 * inv * g[t]       + b[t];
    float o1 = d1 * inv * g[t + 256] + b[t + 256];
    float o2 = d2 * inv * g[t + 512] + b[t + 512];
    float o3 = d3 * inv * g[t + 768] + b[t + 768];
    y[base + t] = o0; y[base + t + 256] = o1; y[base + t + 512] = o2; y[base + t + 768] = o3;
    if (EMIT) {
        split2(o0, yh[base + t],       yl[base + t]);
        split2(o1, yh[base + t + 256], yl[base + t + 256]);
        split2(o2, yh[base + t + 512], yl[base + t + 512]);
        split2(o3, yh[base + t + 768], yl[base + t + 768]);
    }
}

// ---------------- elementwise ----------------
__global__ __launch_bounds__(256) void embed_kernel(const int* __restrict__ idx,
                                                    const float* __restrict__ emb,
                                                    float* __restrict__ X) {
    int i = blockIdx.x * 256 + threadIdx.x;
    int row = i >> 10, c = i & 1023;
    X[i] = emb[(size_t)idx[row] * C_ + c];
}

__global__ __launch_bounds__(256) void mix_kernel(const float* __restrict__ hs,
                                                  bf16* __restrict__ mh, bf16* __restrict__ ml) {
    int i = blockIdx.x * 256 + threadIdx.x;
    int row = i >> 10, t = row & (T_ - 1);
    float prev = (t == 0) ? 0.f : hs[i - C_];
    split2(0.5f * (hs[i] + prev), mh[i], ml[i]);
}

// r from QKV col [0,C), st from g_ST
__global__ __launch_bounds__(256) void rs_kernel(const float* __restrict__ qkv,
                                                 const float* __restrict__ st,
                                                 bf16* __restrict__ oh, bf16* __restrict__ ol) {
    int i = blockIdx.x * 256 + threadIdx.x;
    int row = i >> 10, c = i & 1023;
    float r = qkv[(size_t)row * QW + c];
    split2(r * st[i], oh[i], ol[i]);
}

// ---------------- RWKV scan (k,v read from strided QKV) ----------------
__global__ __launch_bounds__(256) void scan1_kernel(const float* __restrict__ qkv,
                                                    float* __restrict__ part) {
    int g = blockIdx.x * 256 + threadIdx.x;
    int c = g & (C_ - 1), ch = (g >> 10) & (NCH - 1), b = g >> 15;
    size_t row = (size_t)(b * T_ + ch * CHL);
    float s = 0.f;
#pragma unroll 4
    for (int j = 0; j < CHL; j++) {
        const float* q = qkv + (row + j) * QW;
        s += q[C_ + c] * q[2 * C_ + c];
    }
    part[g] = s;
}

__global__ __launch_bounds__(256) void scan2_kernel(float* __restrict__ part) {
    int g = blockIdx.x * 256 + threadIdx.x;
    int c = g & (C_ - 1), b = g >> 10;
    float run = 0.f;
#pragma unroll
    for (int ch = 0; ch < NCH; ch++) {
        size_t i = ((size_t)(b * NCH + ch)) * C_ + c;
        float tv = part[i]; part[i] = run; run += tv;
    }
}

__global__ __launch_bounds__(256) void scan3_kernel(const float* __restrict__ qkv,
                                                    const float* __restrict__ part,
                                                    float* __restrict__ st,
                                                    bf16* __restrict__ sh, bf16* __restrict__ sl) {
    int g = blockIdx.x * 256 + threadIdx.x;
    int c = g & (C_ - 1), ch = (g >> 10) & (NCH - 1), b = g >> 15;
    size_t row = (size_t)(b * T_ + ch * CHL);
    size_t obase = row * C_ + c;
    float run = part[g];
#pragma unroll 4
    for (int j = 0; j < CHL; j++) {
        const float* q = qkv + (row + j) * QW;
        run += q[C_ + c] * q[2 * C_ + c];
        float v = run / (float)(ch * CHL + j + 1);
        st[obase] = v;
        split2(v, sh[obase], sl[obase]);
        obase += C_;
    }
}

// ---------------- router (fp32) ----------------
__global__ __launch_bounds__(256) void route_kernel(const float* __restrict__ Hh,
                                                    const float* __restrict__ wconf,
                                                    const float* __restrict__ waff,
                                                    const float* __restrict__ shares,
                                                    int* __restrict__ win,
                                                    float* __restrict__ scale) {
    int token = blockIdx.x * 8 + (threadIdx.x >> 5);
    int lane = threadIdx.x & 31;
    const float* h = Hh + (size_t)token * C_;
    float sc0 = 0, sc1 = 0, sc2 = 0, sa0 = 0, sa1 = 0, sa2 = 0;
    for (int c = lane; c < C_; c += 32) {
        float hv = h[c];
        sc0 = fmaf(hv, wconf[c], sc0);
        sc1 = fmaf(hv, wconf[C_ + c], sc1);
        sc2 = fmaf(hv, wconf[2 * C_ + c], sc2);
        sa0 = fmaf(hv, waff[c * E_ + 0], sa0);
        sa1 = fmaf(hv, waff[c * E_ + 1], sa1);
        sa2 = fmaf(hv, waff[c * E_ + 2], sa2);
    }
#pragma unroll
    for (int o = 16; o > 0; o >>= 1) {
        sc0 += __shfl_xor_sync(0xffffffffu, sc0, o);
        sc1 += __shfl_xor_sync(0xffffffffu, sc1, o);
        sc2 += __shfl_xor_sync(0xffffffffu, sc2, o);
        sa0 += __shfl_xor_sync(0xffffffffu, sa0, o);
        sa1 += __shfl_xor_sync(0xffffffffu, sa1, o);
        sa2 += __shfl_xor_sync(0xffffffffu, sa2, o);
    }
    if (lane == 0) {
        float c0 = 1.f / (1.f + expf(-sc0));
        float c1 = 1.f / (1.f + expf(-sc1));
        float c2 = 1.f / (1.f + expf(-sc2));
        float b0 = c0 * shares[0] + sa0;
        float b1 = c1 * shares[1] + sa1;
        float b2 = c2 * shares[2] + sa2;
        int w = 0; float bb = b0, cw = c0;
        if (b1 > bb) { bb = b1; w = 1; cw = c1; }
        if (b2 > bb) { bb = b2; w = 2; cw = c2; }
        win[token] = w;
        scale[token] = cw / (cw + 1e-6f);
    }
}

// ---------------- MoE dispatch ----------------
__global__ void zero_cnt_kernel() {
    if (threadIdx.x < E_) g_CNT[threadIdx.x] = 0;
}

__global__ __launch_bounds__(256) void compact_kernel(const int* __restrict__ win) {
    int t = blockIdx.x * 256 + threadIdx.x;
    int w = win[t];
    int pos = atomicAdd(&g_CNT[w], 1);
    g_LIST[w][pos] = t;
}

__global__ __launch_bounds__(256) void gather_kernel(const bf16* __restrict__ sh,
                                                     const bf16* __restrict__ sl,
                                                     bf16* __restrict__ dh, bf16* __restrict__ dl,
                                                     const int* __restrict__ list,
                                                     const int* __restrict__ cnt) {
    int row = blockIdx.x * 8 + (threadIdx.x >> 5);
    if (row >= *cnt) return;
    int lane = threadIdx.x & 31;
    int tok = list[row];
    const uint4* s0 = (const uint4*)(sh + (size_t)tok * C_);
    const uint4* s1 = (const uint4*)(sl + (size_t)tok * C_);
    uint4* d0 = (uint4*)(dh + (size_t)row * C_);
    uint4* d1 = (uint4*)(dl + (size_t)row * C_);
    for (int i = lane; i < C_ / 8; i += 32) { d0[i] = s0[i]; d1[i] = s1[i]; }
}

// gather concat(h, state) into 2C-wide rows
__global__ __launch_bounds__(256) void gather2_kernel(const bf16* __restrict__ hh,
                                                      const bf16* __restrict__ hl,
                                                      const bf16* __restrict__ sh,
                                                      const bf16* __restrict__ sl,
                                                      bf16* __restrict__ dh, bf16* __restrict__ dl,
                                                      const int* __restrict__ list,
                                                      const int* __restrict__ cnt) {
    int row = blockIdx.x * 8 + (threadIdx.x >> 5);
    if (row >= *cnt) return;
    int lane = threadIdx.x & 31;
    int tok = list[row];
    const uint4* h0 = (const uint4*)(hh + (size_t)tok * C_);
    const uint4* h1 = (const uint4*)(hl + (size_t)tok * C_);
    const uint4* s0 = (const uint4*)(sh + (size_t)tok * C_);
    const uint4* s1 = (const uint4*)(sl + (size_t)tok * C_);
    uint4* d0 = (uint4*)(dh + (size_t)row * 2 * C_);
    uint4* d1 = (uint4*)(dl + (size_t)row * 2 * C_);
    const int nv = C_ / 8;
    for (int i = lane; i < nv; i += 32) {
        d0[i] = h0[i];      d1[i] = h1[i];
        d0[nv + i] = s0[i]; d1[nv + i] = s1[i];
    }
}

__global__ __launch_bounds__(256) void scatter_kernel(float* __restrict__ X,
                                                      const float* __restrict__ EC,
                                                      const int* __restrict__ list,
                                                      const int* __restrict__ cnt,
                                                      const float* __restrict__ scale) {
    int row = blockIdx.x * 8 + (threadIdx.x >> 5);
    if (row >= *cnt) return;
    int lane = threadIdx.x & 31;
    int tok = list[row];
    float sc = scale[tok];
    const float4* s = (const float4*)(EC + (size_t)row * C_);
    float4* d = (float4*)(X + (size_t)tok * C_);
    for (int i = lane; i < C_ / 4; i += 32) {
        float4 v = s[i]; float4 o = d[i];
        o.x += v.x * sc; o.y += v.y * sc; o.z += v.z * sc; o.w += v.w * sc;
        d[i] = o;
    }
}

// ---- weight transpose+split: in [z][K][N] f32 -> out [z-stride ostride][N][K] bf16 hi/lo
__global__ __launch_bounds__(256) void wt_kernel(const float* __restrict__ in,
                                                 bf16* __restrict__ oh, bf16* __restrict__ ol,
                                                 int K, int N, size_t ostride) {
    __shared__ float t[32][33];
    int z = blockIdx.z;
    const float* ip = in + (size_t)z * K * N;
    int n0 = blockIdx.x * 32, k0 = blockIdx.y * 32;
    int tx = threadIdx.x, ty = threadIdx.y;
#pragma unroll
    for (int j = 0; j < 32; j += 8)
        t[ty + j][tx] = ip[(size_t)(k0 + ty + j) * N + n0 + tx];
    __syncthreads();
    size_t ob = (size_t)z * ostride;
#pragma unroll
    for (int j = 0; j < 32; j += 8) {
        size_t o = ob + (size_t)(n0 + ty + j) * K + k0 + tx;
        split2(t[tx][ty + j], oh[o], ol[o]);
    }
}

// ---------------------------------------------------------------------------
// bf16x3 tensor-core GEMM — EXACT round-10 configuration:
// CTA 128x128, 8 warps of 64x32, BK=32, 2-stage cp.async ping-pong,
// grid(N/128, M/128) with m0 = blockIdx.y. New OP_QKV epilogue only.
// ---------------------------------------------------------------------------
enum { OP_NONE = 0, OP_SIG = 1, OP_RELU = 2, OP_ADD = 3, OP_ADDRELU = 4, OP_QKV = 5 };

#define PADK 40
#define PLANE_B (128 * PADK * 2)
#define SMEM_BYTES (8 * PLANE_B)

__device__ __forceinline__ uint32_t s2u(const void* p) {
    uint32_t a;
    asm("{ .reg .u64 t; cvta.to.shared.u64 t, %1; cvt.u32.u64 %0, t; }" : "=r"(a) : "l"(p));
    return a;
}
__device__ __forceinline__ void cpa16(uint32_t d, const void* s) {
    asm volatile("cp.async.cg.shared.global [%0], [%1], 16;" :: "r"(d), "l"(s));
}
__device__ __forceinline__ void ldsm4(uint32_t* r, uint32_t a) {
    asm volatile("ldmatrix.sync.aligned.m8n8.x4.shared.b16 {%0,%1,%2,%3}, [%4];"
                 : "=r"(r[0]), "=r"(r[1]), "=r"(r[2]), "=r"(r[3]) : "r"(a));
}
__device__ __forceinline__ void mma_bf16(float* c, const uint32_t* a, uint32_t b0, uint32_t b1) {
    asm volatile(
        "mma.sync.aligned.m16n8k16.row.col.f32.bf16.bf16.f32 "
        "{%0,%1,%2,%3}, {%4,%5,%6,%7}, {%8,%9}, {%0,%1,%2,%3};"
        : "+f"(c[0]), "+f"(c[1]), "+f"(c[2]), "+f"(c[3])
        : "r"(a[0]), "r"(a[1]), "r"(a[2]), "r"(a[3]), "r"(b0), "r"(b1));
}

template <int OP, int WB>
__global__ __launch_bounds__(256) void hgemm_kernel(
        const bf16* __restrict__ Ahp, const bf16* __restrict__ Alp,
        const bf16* __restrict__ Bhp, const bf16* __restrict__ Blp,
        const float* __restrict__ Cin, float* __restrict__ Cout,
        bf16* __restrict__ Eh, bf16* __restrict__ El,
        const int* __restrict__ cntp,
        int M, int N, int K, int ldb) {
    const int m0 = blockIdx.y * 128, n0 = blockIdx.x * 128;
    if (cntp && m0 >= *cntp) return;
    extern __shared__ __align__(16) char smem[];
    const uint32_t uS = s2u(smem);
    const int tid = threadIdx.x, wid = tid >> 5, lane = tid & 31;
    const int nk = K >> 5;

    const int lrow = tid >> 1, lhalf = tid & 1;
    const bf16* gA[2] = { Ahp + (size_t)(m0 + lrow) * K + lhalf * 16,
                          Alp + (size_t)(m0 + lrow) * K + lhalf * 16 };
    const bf16* gB[2] = { Bhp + (size_t)(n0 + lrow) * ldb + lhalf * 16,
                          Blp + (size_t)(n0 + lrow) * ldb + lhalf * 16 };
    const uint32_t sOff = (lrow * PADK + lhalf * 16) * 2;

#define LOAD_STAGE(s, kt) do {                                            \
        size_t ko = (size_t)(kt) * 32;                                    \
        uint32_t sb = uS + (s) * 4 * PLANE_B + sOff;                      \
        cpa16(sb,                gA[0] + ko);                             \
        cpa16(sb + 16,           gA[0] + ko + 8);                         \
        cpa16(sb + PLANE_B,      gA[1] + ko);                             \
        cpa16(sb + PLANE_B + 16, gA[1] + ko + 8);                         \
        cpa16(sb + 2 * PLANE_B,      gB[0] + ko);                         \
        cpa16(sb + 2 * PLANE_B + 16, gB[0] + ko + 8);                     \
        cpa16(sb + 3 * PLANE_B,      gB[1] + ko);                         \
        cpa16(sb + 3 * PLANE_B + 16, gB[1] + ko + 8);                     \
        asm volatile("cp.async.commit_group;" ::: "memory");              \
    } while (0)

    float acc[4][4][4];
#pragma unroll
    for (int i = 0; i < 4; i++)
#pragma unroll
        for (int j = 0; j < 4; j++)
#pragma unroll
            for (int q = 0; q < 4; q++) acc[i][j][q] = 0.f;

    const int mB = (wid & 1) * 64, nB = (wid >> 1) * 32;
    const int lane16 = lane & 15, laneHi = lane >> 4;
    const uint32_t aFrag = ((mB + lane16) * PADK + laneHi * 8) * 2;
    const uint32_t bFrag = ((nB + lane16) * PADK + laneHi * 8) * 2;

    LOAD_STAGE(0, 0);

    for (int kt = 0; kt < nk; kt++) {
        const int s = kt & 1;
        asm volatile("cp.async.wait_group 0;" ::: "memory");
        __syncthreads();
        if (kt + 1 < nk) LOAD_STAGE(s ^ 1, kt + 1);

        const uint32_t pAh = uS + s * 4 * PLANE_B;
        const uint32_t pAl = pAh + PLANE_B;
        const uint32_t pBh = pAh + 2 * PLANE_B;
        const uint32_t pBl = pAh + 3 * PLANE_B;
#pragma unroll
        for (int kk = 0; kk < 2; kk++) {
            const uint32_t k0b = kk * 32;
            uint32_t ah[4][4], al[4][4], bh[2][4], bl[2][4];
#pragma unroll
            for (int i = 0; i < 4; i++) {
                ldsm4(ah[i], pAh + aFrag + k0b + i * (16 * PADK * 2));
                ldsm4(al[i], pAl + aFrag + k0b + i * (16 * PADK * 2));
            }
#pragma unroll
            for (int jj = 0; jj < 2; jj++) {
                ldsm4(bh[jj], pBh + bFrag + k0b + jj * (16 * PADK * 2));
                ldsm4(bl[jj], pBl + bFrag + k0b + jj * (16 * PADK * 2));
            }
#pragma unroll
            for (int j = 0; j < 4; j++) {
                const int jj = j >> 1, t = j & 1;
                const uint32_t bh0 = bh[jj][t], bh1 = bh[jj][2 + t];
                const uint32_t bl0 = bl[jj][t], bl1 = bl[jj][2 + t];
#pragma unroll
                for (int i = 0; i < 4; i++) {
                    mma_bf16(acc[i][j], ah[i], bh0, bh1);
                    mma_bf16(acc[i][j], ah[i], bl0, bl1);
                    mma_bf16(acc[i][j], al[i], bh0, bh1);
                }
            }
        }
        __syncthreads();
    }

    const int lr = lane >> 2, lc = lane & 3;
    const bool qkvsig = (OP == OP_QKV) && (n0 < C_);
#pragma unroll
    for (int i = 0; i < 4; i++)
#pragma unroll
        for (int j = 0; j < 4; j++)
#pragma unroll
            for (int h = 0; h < 2; h++) {
                int row = m0 + mB + i * 16 + lr + h * 8;
                int col = n0 + nB + j * 8 + lc * 2;
                float v0 = acc[i][j][h * 2 + 0];
                float v1 = acc[i][j][h * 2 + 1];
                if (OP == OP_SIG) {
                    v0 = 1.f / (1.f + expf(-v0)); v1 = 1.f / (1.f + expf(-v1));
                } else if (OP == OP_QKV) {
                    if (qkvsig) { v0 = 1.f / (1.f + expf(-v0)); v1 = 1.f / (1.f + expf(-v1)); }
                } else if (OP == OP_RELU) {
                    v0 = fmaxf(v0, 0.f); v1 = fmaxf(v1, 0.f);
                } else if (OP == OP_ADD) {
                    float2 o = *(const float2*)&Cin[(size_t)row * N + col];
                    v0 += o.x; v1 += o.y;
                } else if (OP == OP_ADDRELU) {
                    float2 o = *(const float2*)&Cin[(size_t)row * N + col];
                    v0 = fmaxf(v0 + o.x, 0.f); v1 = fmaxf(v1 + o.y, 0.f);
                }
                if (WB) {
                    bf16 h0, l0, h1, l1;
                    split2(v0, h0, l0); split2(v1, h1, l1);
                    size_t o = (size_t)row * N + col;
                    *(__nv_bfloat162*)&Eh[o] = __halves2bfloat162(h0, h1);
                    *(__nv_bfloat162*)&El[o] = __halves2bfloat162(l0, l1);
                } else {
                    *(float2*)&Cout[(size_t)row * N + col] = make_float2(v0, v1);
                }
            }
}

static void gemm(int op, const bf16* Ah, const bf16* Al, const bf16* Bh, const bf16* Bl,
                 const float* Cin, float* Cout, bf16* Eh, bf16* El, const int* cntp,
                 int M, int N, int K, int ldb) {
    dim3 grid(N / 128, M / 128), block(256);
    switch (op) {
        case OP_NONE:
            cudaFuncSetAttribute(hgemm_kernel<OP_NONE, 0>, cudaFuncAttributeMaxDynamicSharedMemorySize, SMEM_BYTES);
            hgemm_kernel<OP_NONE, 0><<<grid, block, SMEM_BYTES>>>(Ah, Al, Bh, Bl, Cin, Cout, Eh, El, cntp, M, N, K, ldb);
            break;
        case OP_QKV:
            cudaFuncSetAttribute(hgemm_kernel<OP_QKV, 0>, cudaFuncAttributeMaxDynamicSharedMemorySize, SMEM_BYTES);
            hgemm_kernel<OP_QKV, 0><<<grid, block, SMEM_BYTES>>>(Ah, Al, Bh, Bl, Cin, Cout, Eh, El, cntp, M, N, K, ldb);
            break;
        case OP_ADD:
            cudaFuncSetAttribute(hgemm_kernel<OP_ADD, 0>, cudaFuncAttributeMaxDynamicSharedMemorySize, SMEM_BYTES);
            hgemm_kernel<OP_ADD, 0><<<grid, block, SMEM_BYTES>>>(Ah, Al, Bh, Bl, Cin, Cout, Eh, El, cntp, M, N, K, ldb);
            break;
        case OP_RELU:
            cudaFuncSetAttribute(hgemm_kernel<OP_RELU, 1>, cudaFuncAttributeMaxDynamicSharedMemorySize, SMEM_BYTES);
            hgemm_kernel<OP_RELU, 1><<<grid, block, SMEM_BYTES>>>(Ah, Al, Bh, Bl, Cin, Cout, Eh, El, cntp, M, N, K, ldb);
            break;
    }
}

// ---------------- host orchestration ----------------
extern "C" void kernel_launch(void* const* d_in, const int* in_sizes, int n_in,
                              void* d_out, int out_size) {
    (void)in_sizes; (void)n_in; (void)out_size;
    const int*   idx    = (const int*)d_in[0];
    const float* shares = (const float*)d_in[1];
    const float* emb    = (const float*)d_in[2];
    const float* ln1_g  = (const float*)d_in[3];
    const float* ln1_b  = (const float*)d_in[4];
    const float* ln2_g  = (const float*)d_in[5];
    const float* ln2_b  = (const float*)d_in[6];
    const float* Wr     = (const float*)d_in[7];
    const float* Wk     = (const float*)d_in[8];
    const float* Wv     = (const float*)d_in[9];
    const float* Wo     = (const float*)d_in[10];
    const float* W1     = (const float*)d_in[11];
    const float* W2     = (const float*)d_in[12];
    const float* w_conf = (const float*)d_in[13];
    const float* Wl1    = (const float*)d_in[14];
    const float* Wl2    = (const float*)d_in[15];
    /* d_in[16] = W_diff unused */
    const float* W_aff  = (const float*)d_in[17];
    const float* lnf_g  = (const float*)d_in[18];
    const float* lnf_b  = (const float*)d_in[19];
    const float* head_W = (const float*)d_in[20];

    float *X, *HS, *ST, *Hh, *QKV, *EC, *PART, *SCL;
    int *WIN, *CNT, *LIST;
    cudaGetSymbolAddress((void**)&X, g_X);     cudaGetSymbolAddress((void**)&HS, g_HS);
    cudaGetSymbolAddress((void**)&ST, g_ST);   cudaGetSymbolAddress((void**)&Hh, g_Hh);
    cudaGetSymbolAddress((void**)&QKV, g_QKV); cudaGetSymbolAddress((void**)&EC, g_EC);
    cudaGetSymbolAddress((void**)&PART, g_PART);
    cudaGetSymbolAddress((void**)&SCL, g_SCL); cudaGetSymbolAddress((void**)&WIN, g_WIN);
    cudaGetSymbolAddress((void**)&CNT, g_CNT); cudaGetSymbolAddress((void**)&LIST, g_LIST);
    bf16 *MIXb, *RSb, *Hb, *STb, *HSb, *FFb, *GA, *GA2;
    cudaGetSymbolAddress((void**)&MIXb, g_MIXb); cudaGetSymbolAddress((void**)&RSb, g_RSb);
    cudaGetSymbolAddress((void**)&Hb, g_Hb);     cudaGetSymbolAddress((void**)&STb, g_STb);
    cudaGetSymbolAddress((void**)&HSb, g_HSb);   cudaGetSymbolAddress((void**)&FFb, g_FFb);
    cudaGetSymbolAddress((void**)&GA, g_GA);     cudaGetSymbolAddress((void**)&GA2, g_GA2);
    bf16 *Wqkv, *WoT, *W1T, *W2T, *Wl1T, *Wl2T, *HT;
    cudaGetSymbolAddress((void**)&Wqkv, g_Wqkv); cudaGetSymbolAddress((void**)&WoT, g_WoT);
    cudaGetSymbolAddress((void**)&W1T, g_W1T);   cudaGetSymbolAddress((void**)&W2T, g_W2T);
    cudaGetSymbolAddress((void**)&Wl1T, g_Wl1T); cudaGetSymbolAddress((void**)&Wl2T, g_Wl2T);
    cudaGetSymbolAddress((void**)&HT, g_HT);

    const size_t PQ  = (size_t)L_ * QW * C_;
    const size_t PW  = (size_t)L_ * C_ * C_;
    const size_t PW1 = (size_t)L_ * 2 * H_ * C_;
    const size_t PW2 = (size_t)L_ * 2 * C_ * H_;
    const size_t PL1 = (size_t)L_ * H_ * 2 * C_;
    const size_t PL2 = (size_t)L_ * C_ * H_;
    const size_t PHT = (size_t)V_ * C_;
    const size_t PA  = (size_t)SZ;
    const size_t PG2 = (size_t)BT * 2 * C_;
    const size_t PF  = (size_t)BT * H_;

    dim3 tb(32, 8);
    const size_t QS = (size_t)QW * C_;  // per-layer stride inside Wqkv
    wt_kernel<<<dim3(C_ / 32, C_ / 32, L_), tb>>>(Wr, Wqkv,                 Wqkv + PQ,                 C_, C_, QS);
    wt_kernel<<<dim3(C_ / 32, C_ / 32, L_), tb>>>(Wk, Wqkv + (size_t)C_ * C_,     Wqkv + PQ + (size_t)C_ * C_,     C_, C_, QS);
    wt_kernel<<<dim3(C_ / 32, C_ / 32, L_), tb>>>(Wv, Wqkv + (size_t)2 * C_ * C_, Wqkv + PQ + (size_t)2 * C_ * C_, C_, C_, QS);
    wt_kernel<<<dim3(C_ / 32, C_ / 32, L_), tb>>>(Wo, WoT, WoT + PW, C_, C_, (size_t)C_ * C_);
    wt_kernel<<<dim3(H_ / 32, C_ / 32, L_ * 2), tb>>>(W1, W1T, W1T + PW1, C_, H_, (size_t)C_ * H_);
    wt_kernel<<<dim3(C_ / 32, H_ / 32, L_ * 2), tb>>>(W2, W2T, W2T + PW2, H_, C_, (size_t)H_ * C_);
    wt_kernel<<<dim3(H_ / 32, (2 * C_) / 32, L_), tb>>>(Wl1, Wl1T, Wl1T + PL1, 2 * C_, H_, (size_t)2 * C_ * H_);
    wt_kernel<<<dim3(C_ / 32, H_ / 32, L_), tb>>>(Wl2, Wl2T, Wl2T + PL2, H_, C_, (size_t)H_ * C_);
    wt_kernel<<<dim3(V_ / 32, C_ / 32, 1), tb>>>(head_W, HT, HT + PHT, C_, V_, (size_t)C_ * V_);

    const int EW = SZ / 256;
    embed_kernel<<<EW, 256>>>(idx, emb, X);

    for (int l = 0; l < L_; l++) {
        const size_t wo = (size_t)l * C_ * C_;
        ln_kernel<0><<<BT, 256>>>(X, HS, nullptr, nullptr, ln1_g + (size_t)l * C_, ln1_b + (size_t)l * C_);
        mix_kernel<<<EW, 256>>>(HS, MIXb, MIXb + PA);
        // fused QKV: one BTx3072 GEMM, sigmoid on first C_ columns
        gemm(OP_QKV, MIXb, MIXb + PA, Wqkv + (size_t)l * QS, Wqkv + PQ + (size_t)l * QS,
             nullptr, QKV, nullptr, nullptr, nullptr, BT, QW, C_, C_);
        scan1_kernel<<<(B_ * NCH * C_) / 256, 256>>>(QKV, PART);
        scan2_kernel<<<(B_ * C_) / 256, 256>>>(PART);
        scan3_kernel<<<(B_ * NCH * C_) / 256, 256>>>(QKV, PART, ST, STb, STb + PA);
        rs_kernel<<<EW, 256>>>(QKV, ST, RSb, RSb + PA);
        gemm(OP_ADD, RSb, RSb + PA, WoT + wo, WoT + PW + wo, X, X, nullptr, nullptr, nullptr, BT, C_, C_, C_);
        ln_kernel<1><<<BT, 256>>>(X, Hh, Hb, Hb + PA, ln2_g + (size_t)l * C_, ln2_b + (size_t)l * C_);
        route_kernel<<<BT / 8, 256>>>(Hh, w_conf + (size_t)l * E_ * C_,
                                      W_aff + (size_t)l * C_ * E_,
                                      shares + (size_t)l * E_, WIN, SCL);
        zero_cnt_kernel<<<1, 32>>>();
        compact_kernel<<<BT / 256, 256>>>(WIN);

        for (int e = 0; e < 2; e++) {
            const int* cnt_e = CNT + e;
            const int* list_e = LIST + (size_t)e * BT;
            const size_t w1o = ((size_t)l * 2 + e) * H_ * C_;
            const size_t w2o = ((size_t)l * 2 + e) * C_ * H_;
            gather_kernel<<<BT / 8, 256>>>(Hb, Hb + PA, GA, GA + PA, list_e, cnt_e);
            gemm(OP_RELU, GA, GA + PA, W1T + w1o, W1T + PW1 + w1o, nullptr, nullptr,
                 FFb, FFb + PF, cnt_e, BT, H_, C_, C_);
            gemm(OP_NONE, FFb, FFb + PF, W2T + w2o, W2T + PW2 + w2o, nullptr, EC,
                 nullptr, nullptr, cnt_e, BT, C_, H_, H_);
            scatter_kernel<<<BT / 8, 256>>>(X, EC, list_e, cnt_e, SCL);
        }

        {
            const int* cnt_e = CNT + 2;
            const int* list_e = LIST + (size_t)2 * BT;
            const size_t l1o = (size_t)l * H_ * 2 * C_;
            const size_t l2o = (size_t)l * C_ * H_;
            gather2_kernel<<<BT / 8, 256>>>(Hb, Hb + PA, STb, STb + PA, GA2, GA2 + PG2, list_e, cnt_e);
            gemm(OP_RELU, GA2, GA2 + PG2, Wl1T + l1o, Wl1T + PL1 + l1o, nullptr, nullptr,
                 FFb, FFb + PF, cnt_e, BT, H_, 2 * C_, 2 * C_);
            gemm(OP_NONE, FFb, FFb + PF, Wl2T + l2o, Wl2T + PL2 + l2o, nullptr, EC,
                 nullptr, nullptr, cnt_e, BT, C_, H_, H_);
            scatter_kernel<<<BT / 8, 256>>>(X, EC, list_e, cnt_e, SCL);
        }
    }

    ln_kernel<1><<<BT, 256>>>(X, HS, HSb, HSb + PA, lnf_g, lnf_b);
    gemm(OP_NONE, HSb, HSb + PA, HT, HT + PHT, nullptr, (float*)d_out, nullptr, nullptr, nullptr, BT, V_, C_, C_);
}

// round 16
// speedup vs baseline: 1.4114x; 1.1470x over previous
#include <cuda_runtime.h>
#include <cuda_bf16.h>
#include <cstdint>
#include <math.h>

#define B_ 2
#define T_ 2048
#define BT 4096
#define C_ 1024
#define QW 3072
#define V_ 32000
#define L_ 4
#define E_ 3
#define H_ 4096
#define NCH 32
#define CHL 64
#define SZ (BT*C_)

typedef __nv_bfloat16 bf16;

// ---------------- static scratch (no allocations) ----------------
__device__ float g_X[SZ], g_HS[SZ], g_ST[SZ], g_Hh[SZ];
__device__ float g_QKV[(size_t)BT * QW];
__device__ float g_EC[(size_t)E_ * SZ];               // per-expert compacted outputs
__device__ float g_PART[B_ * NCH * C_], g_SCL[BT];
__device__ int   g_WIN[BT];
__device__ int   g_CNT[E_];
__device__ int   g_LIST[E_][BT];

__device__ bf16 g_MIXb[2][SZ], g_RSb[2][SZ], g_Hb[2][SZ], g_STb[2][SZ], g_HSb[2][SZ];
__device__ bf16 g_GA[2][(size_t)2 * SZ];              // gathered h rows, experts 0/1
__device__ bf16 g_GA2[2][(size_t)BT * 2 * C_];        // gathered concat(h,state), expert 2
__device__ bf16 g_FFb[2][(size_t)E_ * BT * H_];       // per-expert intermediates

__device__ bf16 g_Wqkv[2][(size_t)L_ * QW * C_];
__device__ bf16 g_WoT[2][(size_t)L_ * C_ * C_];
__device__ bf16 g_W1T[2][(size_t)L_ * 2 * H_ * C_], g_W2T[2][(size_t)L_ * 2 * C_ * H_];
__device__ bf16 g_Wl1T[2][(size_t)L_ * H_ * 2 * C_], g_Wl2T[2][(size_t)L_ * C_ * H_];
__device__ bf16 g_HT[2][(size_t)V_ * C_];

__device__ __forceinline__ void split2(float x, bf16& h, bf16& l) {
    h = __float2bfloat16(x);
    l = __float2bfloat16(x - __bfloat162float(h));
}

// ---------------- block reduce / LN ----------------
__device__ __forceinline__ float blockReduceSum(float val) {
    __shared__ float sh[8];
    int lane = threadIdx.x & 31, w = threadIdx.x >> 5;
#pragma unroll
    for (int o = 16; o > 0; o >>= 1) val += __shfl_xor_sync(0xffffffffu, val, o);
    if (lane == 0) sh[w] = val;
    __syncthreads();
    if (w == 0) {
        float v2 = (lane < 8) ? sh[lane] : 0.f;
#pragma unroll
        for (int o = 4; o > 0; o >>= 1) v2 += __shfl_xor_sync(0xffffffffu, v2, o);
        if (lane == 0) sh[0] = v2;
    }
    __syncthreads();
    float r = sh[0];
    __syncthreads();
    return r;
}

template <int EMIT>
__global__ __launch_bounds__(256) void ln_kernel(const float* __restrict__ x,
                                                 float* __restrict__ y,
                                                 bf16* __restrict__ yh, bf16* __restrict__ yl,
                                                 const float* __restrict__ g,
                                                 const float* __restrict__ b) {
    int row = blockIdx.x;
    const float* xr = x + (size_t)row * C_;
    int t = threadIdx.x;
    float v0 = xr[t], v1 = xr[t + 256], v2 = xr[t + 512], v3 = xr[t + 768];
    float s = blockReduceSum(v0 + v1 + v2 + v3);
    float mean = s * (1.f / C_);
    float d0 = v0 - mean, d1 = v1 - mean, d2 = v2 - mean, d3 = v3 - mean;
    float s2 = blockReduceSum(d0 * d0 + d1 * d1 + d2 * d2 + d3 * d3);
    float inv = rsqrtf(s2 * (1.f / C_) + 1e-5f);
    size_t base = (size_t)row * C_;
    float o0 = d0 * inv * g[t]       + b[t];
    float o1 = d1 * inv * g[t + 256] + b[t + 256];
    float o2 = d2 * inv * g[t + 512] + b[t + 512];
    float o3 = d3 * inv * g[t + 768] + b[t + 768];
    y[base + t] = o0; y[base + t + 256] = o1; y[base + t + 512] = o2; y[base + t + 768] = o3;
    if (EMIT) {
        split2(o0, yh[base + t],       yl[base + t]);
        split2(o1, yh[base + t + 256], yl[base + t + 256]);
        split2(o2, yh[base + t + 512], yl[base + t + 512]);
        split2(o3, yh[base + t + 768], yl[base + t + 768]);
    }
}

// ---------------- elementwise ----------------
__global__ __launch_bounds__(256) void embed_kernel(const int* __restrict__ idx,
                                                    const float* __restrict__ emb,
                                                    float* __restrict__ X) {
    int i = blockIdx.x * 256 + threadIdx.x;
    int row = i >> 10, c = i & 1023;
    X[i] = emb[(size_t)idx[row] * C_ + c];
}

__global__ __launch_bounds__(256) void mix_kernel(const float* __restrict__ hs,
                                                  bf16* __restrict__ mh, bf16* __restrict__ ml) {
    int i = blockIdx.x * 256 + threadIdx.x;
    int row = i >> 10, t = row & (T_ - 1);
    float prev = (t == 0) ? 0.f : hs[i - C_];
    split2(0.5f * (hs[i] + prev), mh[i], ml[i]);
}

__global__ __launch_bounds__(256) void rs_kernel(const float* __restrict__ qkv,
                                                 const float* __restrict__ st,
                                                 bf16* __restrict__ oh, bf16* __restrict__ ol) {
    int i = blockIdx.x * 256 + threadIdx.x;
    int row = i >> 10, c = i & 1023;
    float r = qkv[(size_t)row * QW + c];
    split2(r * st[i], oh[i], ol[i]);
}

// ---------------- RWKV scan (k,v from strided QKV) ----------------
__global__ __launch_bounds__(256) void scan1_kernel(const float* __restrict__ qkv,
                                                    float* __restrict__ part) {
    int g = blockIdx.x * 256 + threadIdx.x;
    int c = g & (C_ - 1), ch = (g >> 10) & (NCH - 1), b = g >> 15;
    size_t row = (size_t)(b * T_ + ch * CHL);
    float s = 0.f;
#pragma unroll 4
    for (int j = 0; j < CHL; j++) {
        const float* q = qkv + (row + j) * QW;
        s += q[C_ + c] * q[2 * C_ + c];
    }
    part[g] = s;
}

__global__ __launch_bounds__(256) void scan2_kernel(float* __restrict__ part) {
    int g = blockIdx.x * 256 + threadIdx.x;
    int c = g & (C_ - 1), b = g >> 10;
    float run = 0.f;
#pragma unroll
    for (int ch = 0; ch < NCH; ch++) {
        size_t i = ((size_t)(b * NCH + ch)) * C_ + c;
        float tv = part[i]; part[i] = run; run += tv;
    }
}

__global__ __launch_bounds__(256) void scan3_kernel(const float* __restrict__ qkv,
                                                    const float* __restrict__ part,
                                                    float* __restrict__ st,
                                                    bf16* __restrict__ sh, bf16* __restrict__ sl) {
    int g = blockIdx.x * 256 + threadIdx.x;
    int c = g & (C_ - 1), ch = (g >> 10) & (NCH - 1), b = g >> 15;
    size_t row = (size_t)(b * T_ + ch * CHL);
    size_t obase = row * C_ + c;
    float run = part[g];
#pragma unroll 4
    for (int j = 0; j < CHL; j++) {
        const float* q = qkv + (row + j) * QW;
        run += q[C_ + c] * q[2 * C_ + c];
        float v = run / (float)(ch * CHL + j + 1);
        st[obase] = v;
        split2(v, sh[obase], sl[obase]);
        obase += C_;
    }
}

// ---------------- router (fp32) ----------------
__global__ __launch_bounds__(256) void route_kernel(const float* __restrict__ Hh,
                                                    const float* __restrict__ wconf,
                                                    const float* __restrict__ waff,
                                                    const float* __restrict__ shares,
                                                    int* __restrict__ win,
                                                    float* __restrict__ scale) {
    int token = blockIdx.x * 8 + (threadIdx.x >> 5);
    int lane = threadIdx.x & 31;
    const float* h = Hh + (size_t)token * C_;
    float sc0 = 0, sc1 = 0, sc2 = 0, sa0 = 0, sa1 = 0, sa2 = 0;
    for (int c = lane; c < C_; c += 32) {
        float hv = h[c];
        sc0 = fmaf(hv, wconf[c], sc0);
        sc1 = fmaf(hv, wconf[C_ + c], sc1);
        sc2 = fmaf(hv, wconf[2 * C_ + c], sc2);
        sa0 = fmaf(hv, waff[c * E_ + 0], sa0);
        sa1 = fmaf(hv, waff[c * E_ + 1], sa1);
        sa2 = fmaf(hv, waff[c * E_ + 2], sa2);
    }
#pragma unroll
    for (int o = 16; o > 0; o >>= 1) {
        sc0 += __shfl_xor_sync(0xffffffffu, sc0, o);
        sc1 += __shfl_xor_sync(0xffffffffu, sc1, o);
        sc2 += __shfl_xor_sync(0xffffffffu, sc2, o);
        sa0 += __shfl_xor_sync(0xffffffffu, sa0, o);
        sa1 += __shfl_xor_sync(0xffffffffu, sa1, o);
        sa2 += __shfl_xor_sync(0xffffffffu, sa2, o);
    }
    if (lane == 0) {
        float c0 = 1.f / (1.f + expf(-sc0));
        float c1 = 1.f / (1.f + expf(-sc1));
        float c2 = 1.f / (1.f + expf(-sc2));
        float b0 = c0 * shares[0] + sa0;
        float b1 = c1 * shares[1] + sa1;
        float b2 = c2 * shares[2] + sa2;
        int w = 0; float bb = b0, cw = c0;
        if (b1 > bb) { bb = b1; w = 1; cw = c1; }
        if (b2 > bb) { bb = b2; w = 2; cw = c2; }
        win[token] = w;
        scale[token] = cw / (cw + 1e-6f);
    }
}

// ---------------- MoE dispatch ----------------
__global__ void zero_cnt_kernel() {
    if (threadIdx.x < E_) g_CNT[threadIdx.x] = 0;
}

__global__ __launch_bounds__(256) void compact_kernel(const int* __restrict__ win) {
    int t = blockIdx.x * 256 + threadIdx.x;
    int w = win[t];
    int pos = atomicAdd(&g_CNT[w], 1);
    g_LIST[w][pos] = t;
}

// batched gather for experts 0/1: blockIdx.y = e
__global__ __launch_bounds__(256) void gatherB_kernel(const bf16* __restrict__ sh,
                                                      const bf16* __restrict__ sl,
                                                      bf16* __restrict__ dh, bf16* __restrict__ dl) {
    int e = blockIdx.y;
    int row = blockIdx.x * 8 + (threadIdx.x >> 5);
    if (row >= g_CNT[e]) return;
    int lane = threadIdx.x & 31;
    int tok = g_LIST[e][row];
    const uint4* s0 = (const uint4*)(sh + (size_t)tok * C_);
    const uint4* s1 = (const uint4*)(sl + (size_t)tok * C_);
    uint4* d0 = (uint4*)(dh + ((size_t)e * BT + row) * C_);
    uint4* d1 = (uint4*)(dl + ((size_t)e * BT + row) * C_);
    for (int i = lane; i < C_ / 8; i += 32) { d0[i] = s0[i]; d1[i] = s1[i]; }
}

// gather concat(h, state) for expert 2
__global__ __launch_bounds__(256) void gather2_kernel(const bf16* __restrict__ hh,
                                                      const bf16* __restrict__ hl,
                                                      const bf16* __restrict__ sh,
                                                      const bf16* __restrict__ sl,
                                                      bf16* __restrict__ dh, bf16* __restrict__ dl) {
    int row = blockIdx.x * 8 + (threadIdx.x >> 5);
    if (row >= g_CNT[2]) return;
    int lane = threadIdx.x & 31;
    int tok = g_LIST[2][row];
    const uint4* h0 = (const uint4*)(hh + (size_t)tok * C_);
    const uint4* h1 = (const uint4*)(hl + (size_t)tok * C_);
    const uint4* s0 = (const uint4*)(sh + (size_t)tok * C_);
    const uint4* s1 = (const uint4*)(sl + (size_t)tok * C_);
    uint4* d0 = (uint4*)(dh + (size_t)row * 2 * C_);
    uint4* d1 = (uint4*)(dl + (size_t)row * 2 * C_);
    const int nv = C_ / 8;
    for (int i = lane; i < nv; i += 32) {
        d0[i] = h0[i];      d1[i] = h1[i];
        d0[nv + i] = s0[i]; d1[nv + i] = s1[i];
    }
}

// batched scatter over all 3 experts: blockIdx.y = e
__global__ __launch_bounds__(256) void scatterB_kernel(float* __restrict__ X,
                                                       const float* __restrict__ EC,
                                                       const float* __restrict__ scale) {
    int e = blockIdx.y;
    int row = blockIdx.x * 8 + (threadIdx.x >> 5);
    if (row >= g_CNT[e]) return;
    int lane = threadIdx.x & 31;
    int tok = g_LIST[e][row];
    float sc = scale[tok];
    const float4* s = (const float4*)(EC + ((size_t)e * BT + row) * C_);
    float4* d = (float4*)(X + (size_t)tok * C_);
    for (int i = lane; i < C_ / 4; i += 32) {
        float4 v = s[i]; float4 o = d[i];
        o.x += v.x * sc; o.y += v.y * sc; o.z += v.z * sc; o.w += v.w * sc;
        d[i] = o;
    }
}

// ---- weight transpose+split ----
__global__ __launch_bounds__(256) void wt_kernel(const float* __restrict__ in,
                                                 bf16* __restrict__ oh, bf16* __restrict__ ol,
                                                 int K, int N, size_t ostride) {
    __shared__ float t[32][33];
    int z = blockIdx.z;
    const float* ip = in + (size_t)z * K * N;
    int n0 = blockIdx.x * 32, k0 = blockIdx.y * 32;
    int tx = threadIdx.x, ty = threadIdx.y;
#pragma unroll
    for (int j = 0; j < 32; j += 8)
        t[ty + j][tx] = ip[(size_t)(k0 + ty + j) * N + n0 + tx];
    __syncthreads();
    size_t ob = (size_t)z * ostride;
#pragma unroll
    for (int j = 0; j < 32; j += 8) {
        size_t o = ob + (size_t)(n0 + ty + j) * K + k0 + tx;
        split2(t[tx][ty + j], oh[o], ol[o]);
    }
}

// ---------------------------------------------------------------------------
// bf16x3 tensor-core GEMM — round-10 inner loop. Z-batched variant selects
// per-z A/B/C regions and per-z token count (expert batching).
// ---------------------------------------------------------------------------
enum { OP_NONE = 0, OP_RELU = 2, OP_ADD = 3, OP_QKV = 5 };

#define PADK 40
#define PLANE_B (128 * PADK * 2)
#define SMEM_BYTES (8 * PLANE_B)

__device__ __forceinline__ uint32_t s2u(const void* p) {
    uint32_t a;
    asm("{ .reg .u64 t; cvta.to.shared.u64 t, %1; cvt.u32.u64 %0, t; }" : "=r"(a) : "l"(p));
    return a;
}
__device__ __forceinline__ void cpa16(uint32_t d, const void* s) {
    asm volatile("cp.async.cg.shared.global [%0], [%1], 16;" :: "r"(d), "l"(s));
}
__device__ __forceinline__ void ldsm4(uint32_t* r, uint32_t a) {
    asm volatile("ldmatrix.sync.aligned.m8n8.x4.shared.b16 {%0,%1,%2,%3}, [%4];"
                 : "=r"(r[0]), "=r"(r[1]), "=r"(r[2]), "=r"(r[3]) : "r"(a));
}
__device__ __forceinline__ void mma_bf16(float* c, const uint32_t* a, uint32_t b0, uint32_t b1) {
    asm volatile(
        "mma.sync.aligned.m16n8k16.row.col.f32.bf16.bf16.f32 "
        "{%0,%1,%2,%3}, {%4,%5,%6,%7}, {%8,%9}, {%0,%1,%2,%3};"
        : "+f"(c[0]), "+f"(c[1]), "+f"(c[2]), "+f"(c[3])
        : "r"(a[0]), "r"(a[1]), "r"(a[2]), "r"(a[3]), "r"(b0), "r"(b1));
}

// Shared mainloop+epilogue body.
template <int OP, int WB>
__device__ __forceinline__ void gemm_body(
        const bf16* Ahp, const bf16* Alp,
        const bf16* Bhp, const bf16* Blp,
        const float* Cin, float* Cout,
        bf16* Eh, bf16* El,
        int m0, int n0, int N, int K, int ldb, char* smem) {
    const uint32_t uS = s2u(smem);
    const int tid = threadIdx.x, wid = tid >> 5, lane = tid & 31;
    const int nk = K >> 5;

    const int lrow = tid >> 1, lhalf = tid & 1;
    const bf16* gA[2] = { Ahp + (size_t)(m0 + lrow) * K + lhalf * 16,
                          Alp + (size_t)(m0 + lrow) * K + lhalf * 16 };
    const bf16* gB[2] = { Bhp + (size_t)(n0 + lrow) * ldb + lhalf * 16,
                          Blp + (size_t)(n0 + lrow) * ldb + lhalf * 16 };
    const uint32_t sOff = (lrow * PADK + lhalf * 16) * 2;

#define LOAD_STAGE(s, kt) do {                                            \
        size_t ko = (size_t)(kt) * 32;                                    \
        uint32_t sb = uS + (s) * 4 * PLANE_B + sOff;                      \
        cpa16(sb,                gA[0] + ko);                             \
        cpa16(sb + 16,           gA[0] + ko + 8);                         \
        cpa16(sb + PLANE_B,      gA[1] + ko);                             \
        cpa16(sb + PLANE_B + 16, gA[1] + ko + 8);                         \
        cpa16(sb + 2 * PLANE_B,      gB[0] + ko);                         \
        cpa16(sb + 2 * PLANE_B + 16, gB[0] + ko + 8);                     \
        cpa16(sb + 3 * PLANE_B,      gB[1] + ko);                         \
        cpa16(sb + 3 * PLANE_B + 16, gB[1] + ko + 8);                     \
        asm volatile("cp.async.commit_group;" ::: "memory");              \
    } while (0)

    float acc[4][4][4];
#pragma unroll
    for (int i = 0; i < 4; i++)
#pragma unroll
        for (int j = 0; j < 4; j++)
#pragma unroll
            for (int q = 0; q < 4; q++) acc[i][j][q] = 0.f;

    const int mB = (wid & 1) * 64, nB = (wid >> 1) * 32;
    const int lane16 = lane & 15, laneHi = lane >> 4;
    const uint32_t aFrag = ((mB + lane16) * PADK + laneHi * 8) * 2;
    const uint32_t bFrag = ((nB + lane16) * PADK + laneHi * 8) * 2;

    LOAD_STAGE(0, 0);

    for (int kt = 0; kt < nk; kt++) {
        const int s = kt & 1;
        asm volatile("cp.async.wait_group 0;" ::: "memory");
        __syncthreads();
        if (kt + 1 < nk) LOAD_STAGE(s ^ 1, kt + 1);

        const uint32_t pAh = uS + s * 4 * PLANE_B;
        const uint32_t pAl = pAh + PLANE_B;
        const uint32_t pBh = pAh + 2 * PLANE_B;
        const uint32_t pBl = pAh + 3 * PLANE_B;
#pragma unroll
        for (int kk = 0; kk < 2; kk++) {
            const uint32_t k0b = kk * 32;
            uint32_t ah[4][4], al[4][4], bh[2][4], bl[2][4];
#pragma unroll
            for (int i = 0; i < 4; i++) {
                ldsm4(ah[i], pAh + aFrag + k0b + i * (16 * PADK * 2));
                ldsm4(al[i], pAl + aFrag + k0b + i * (16 * PADK * 2));
            }
#pragma unroll
            for (int jj = 0; jj < 2; jj++) {
                ldsm4(bh[jj], pBh + bFrag + k0b + jj * (16 * PADK * 2));
                ldsm4(bl[jj], pBl + bFrag + k0b + jj * (16 * PADK * 2));
            }
#pragma unroll
            for (int j = 0; j < 4; j++) {
                const int jj = j >> 1, t = j & 1;
                const uint32_t bh0 = bh[jj][t], bh1 = bh[jj][2 + t];
                const uint32_t bl0 = bl[jj][t], bl1 = bl[jj][2 + t];
#pragma unroll
                for (int i = 0; i < 4; i++) {
                    mma_bf16(acc[i][j], ah[i], bh0, bh1);
                    mma_bf16(acc[i][j], ah[i], bl0, bl1);
                    mma_bf16(acc[i][j], al[i], bh0, bh1);
                }
            }
        }
        __syncthreads();
    }
#undef LOAD_STAGE

    const int lr = lane >> 2, lc = lane & 3;
    const bool qkvsig = (OP == OP_QKV) && (n0 < C_);
#pragma unroll
    for (int i = 0; i < 4; i++)
#pragma unroll
        for (int j = 0; j < 4; j++)
#pragma unroll
            for (int h = 0; h < 2; h++) {
                int row = m0 + mB + i * 16 + lr + h * 8;
                int col = n0 + nB + j * 8 + lc * 2;
                float v0 = acc[i][j][h * 2 + 0];
                float v1 = acc[i][j][h * 2 + 1];
                if (OP == OP_QKV) {
                    if (qkvsig) { v0 = 1.f / (1.f + expf(-v0)); v1 = 1.f / (1.f + expf(-v1)); }
                } else if (OP == OP_RELU) {
                    v0 = fmaxf(v0, 0.f); v1 = fmaxf(v1, 0.f);
                } else if (OP == OP_ADD) {
                    float2 o = *(const float2*)&Cin[(size_t)row * N + col];
                    v0 += o.x; v1 += o.y;
                }
                if (WB) {
                    bf16 h0, l0, h1, l1;
                    split2(v0, h0, l0); split2(v1, h1, l1);
                    size_t o = (size_t)row * N + col;
                    *(__nv_bfloat162*)&Eh[o] = __halves2bfloat162(h0, h1);
                    *(__nv_bfloat162*)&El[o] = __halves2bfloat162(l0, l1);
                } else {
                    *(float2*)&Cout[(size_t)row * N + col] = make_float2(v0, v1);
                }
            }
}

template <int OP, int WB>
__global__ __launch_bounds__(256) void hgemm_kernel(
        const bf16* __restrict__ Ahp, const bf16* __restrict__ Alp,
        const bf16* __restrict__ Bhp, const bf16* __restrict__ Blp,
        const float* __restrict__ Cin, float* __restrict__ Cout,
        bf16* __restrict__ Eh, bf16* __restrict__ El,
        const int* __restrict__ cntp,
        int M, int N, int K, int ldb) {
    const int m0 = blockIdx.y * 128, n0 = blockIdx.x * 128;
    if (cntp && m0 >= *cntp) return;
    extern __shared__ __align__(16) char smem[];
    gemm_body<OP, WB>(Ahp, Alp, Bhp, Blp, Cin, Cout, Eh, El, m0, n0, N, K, ldb, smem);
}

// Z-batched: z selects A region (aStr), B pointer set, C/E regions, cnt.
template <int OP, int WB>
__global__ __launch_bounds__(256) void hgemm_zb_kernel(
        const bf16* __restrict__ Ahp, const bf16* __restrict__ Alp, size_t aStr,
        const bf16* __restrict__ B0h, const bf16* __restrict__ B0l,
        const bf16* __restrict__ B1h, const bf16* __restrict__ B1l,
        const bf16* __restrict__ B2h, const bf16* __restrict__ B2l,
        float* __restrict__ Cout, size_t cStr,
        bf16* __restrict__ Eh, bf16* __restrict__ El, size_t eStr,
        int N, int K, int ldb) {
    const int z = blockIdx.z;
    const int m0 = blockIdx.y * 128, n0 = blockIdx.x * 128;
    if (m0 >= g_CNT[z]) return;
    const bf16* Bh = (z == 0) ? B0h : ((z == 1) ? B1h : B2h);
    const bf16* Bl = (z == 0) ? B0l : ((z == 1) ? B1l : B2l);
    extern __shared__ __align__(16) char smem[];
    gemm_body<OP, WB>(Ahp + (size_t)z * aStr, Alp + (size_t)z * aStr, Bh, Bl,
                      nullptr, Cout ? Cout + (size_t)z * cStr : nullptr,
                      Eh ? Eh + (size_t)z * eStr : nullptr,
                      El ? El + (size_t)z * eStr : nullptr,
                      m0, n0, N, K, ldb, smem);
}

static void gemm(int op, const bf16* Ah, const bf16* Al, const bf16* Bh, const bf16* Bl,
                 const float* Cin, float* Cout, bf16* Eh, bf16* El, const int* cntp,
                 int M, int N, int K, int ldb) {
    dim3 grid(N / 128, M / 128), block(256);
    switch (op) {
        case OP_NONE:
            cudaFuncSetAttribute(hgemm_kernel<OP_NONE, 0>, cudaFuncAttributeMaxDynamicSharedMemorySize, SMEM_BYTES);
            hgemm_kernel<OP_NONE, 0><<<grid, block, SMEM_BYTES>>>(Ah, Al, Bh, Bl, Cin, Cout, Eh, El, cntp, M, N, K, ldb);
            break;
        case OP_QKV:
            cudaFuncSetAttribute(hgemm_kernel<OP_QKV, 0>, cudaFuncAttributeMaxDynamicSharedMemorySize, SMEM_BYTES);
            hgemm_kernel<OP_QKV, 0><<<grid, block, SMEM_BYTES>>>(Ah, Al, Bh, Bl, Cin, Cout, Eh, El, cntp, M, N, K, ldb);
            break;
        case OP_ADD:
            cudaFuncSetAttribute(hgemm_kernel<OP_ADD, 0>, cudaFuncAttributeMaxDynamicSharedMemorySize, SMEM_BYTES);
            hgemm_kernel<OP_ADD, 0><<<grid, block, SMEM_BYTES>>>(Ah, Al, Bh, Bl, Cin, Cout, Eh, El, cntp, M, N, K, ldb);
            break;
        case OP_RELU:
            cudaFuncSetAttribute(hgemm_kernel<OP_RELU, 1>, cudaFuncAttributeMaxDynamicSharedMemorySize, SMEM_BYTES);
            hgemm_kernel<OP_RELU, 1><<<grid, block, SMEM_BYTES>>>(Ah, Al, Bh, Bl, Cin, Cout, Eh, El, cntp, M, N, K, ldb);
            break;
    }
}

// ---------------- host orchestration ----------------
extern "C" void kernel_launch(void* const* d_in, const int* in_sizes, int n_in,
                              void* d_out, int out_size) {
    (void)in_sizes; (void)n_in; (void)out_size;
    const int*   idx    = (const int*)d_in[0];
    const float* shares = (const float*)d_in[1];
    const float* emb    = (const float*)d_in[2];
    const float* ln1_g  = (const float*)d_in[3];
    const float* ln1_b  = (const float*)d_in[4];
    const float* ln2_g  = (const float*)d_in[5];
    const float* ln2_b  = (const float*)d_in[6];
    const float* Wr     = (const float*)d_in[7];
    const float* Wk     = (const float*)d_in[8];
    const float* Wv     = (const float*)d_in[9];
    const float* Wo     = (const float*)d_in[10];
    const float* W1     = (const float*)d_in[11];
    const float* W2     = (const float*)d_in[12];
    const float* w_conf = (const float*)d_in[13];
    const float* Wl1    = (const float*)d_in[14];
    const float* Wl2    = (const float*)d_in[15];
    /* d_in[16] = W_diff unused */
    const float* W_aff  = (const float*)d_in[17];
    const float* lnf_g  = (const float*)d_in[18];
    const float* lnf_b  = (const float*)d_in[19];
    const float* head_W = (const float*)d_in[20];

    float *X, *HS, *ST, *Hh, *QKV, *EC, *PART, *SCL;
    int *WIN, *CNT;
    cudaGetSymbolAddress((void**)&X, g_X);     cudaGetSymbolAddress((void**)&HS, g_HS);
    cudaGetSymbolAddress((void**)&ST, g_ST);   cudaGetSymbolAddress((void**)&Hh, g_Hh);
    cudaGetSymbolAddress((void**)&QKV, g_QKV); cudaGetSymbolAddress((void**)&EC, g_EC);
    cudaGetSymbolAddress((void**)&PART, g_PART);
    cudaGetSymbolAddress((void**)&SCL, g_SCL); cudaGetSymbolAddress((void**)&WIN, g_WIN);
    cudaGetSymbolAddress((void**)&CNT, g_CNT);
    bf16 *MIXb, *RSb, *Hb, *STb, *HSb, *FFb, *GA, *GA2;
    cudaGetSymbolAddress((void**)&MIXb, g_MIXb); cudaGetSymbolAddress((void**)&RSb, g_RSb);
    cudaGetSymbolAddress((void**)&Hb, g_Hb);     cudaGetSymbolAddress((void**)&STb, g_STb);
    cudaGetSymbolAddress((void**)&HSb, g_HSb);   cudaGetSymbolAddress((void**)&FFb, g_FFb);
    cudaGetSymbolAddress((void**)&GA, g_GA);     cudaGetSymbolAddress((void**)&GA2, g_GA2);
    bf16 *Wqkv, *WoT, *W1T, *W2T, *Wl1T, *Wl2T, *HT;
    cudaGetSymbolAddress((void**)&Wqkv, g_Wqkv); cudaGetSymbolAddress((void**)&WoT, g_WoT);
    cudaGetSymbolAddress((void**)&W1T, g_W1T);   cudaGetSymbolAddress((void**)&W2T, g_W2T);
    cudaGetSymbolAddress((void**)&Wl1T, g_Wl1T); cudaGetSymbolAddress((void**)&Wl2T, g_Wl2T);
    cudaGetSymbolAddress((void**)&HT, g_HT);

    const size_t PQ  = (size_t)L_ * QW * C_;
    const size_t PW  = (size_t)L_ * C_ * C_;
    const size_t PW1 = (size_t)L_ * 2 * H_ * C_;
    const size_t PW2 = (size_t)L_ * 2 * C_ * H_;
    const size_t PL1 = (size_t)L_ * H_ * 2 * C_;
    const size_t PL2 = (size_t)L_ * C_ * H_;
    const size_t PHT = (size_t)V_ * C_;
    const size_t PA  = (size_t)SZ;
    const size_t PGA = (size_t)2 * SZ;            // plane stride of g_GA
    const size_t PG2 = (size_t)BT * 2 * C_;
    const size_t PF  = (size_t)E_ * BT * H_;      // plane stride of g_FFb
    const size_t FE  = (size_t)BT * H_;           // per-expert stride inside a plane

    dim3 tb(32, 8);
    const size_t QS = (size_t)QW * C_;
    wt_kernel<<<dim3(C_ / 32, C_ / 32, L_), tb>>>(Wr, Wqkv,                 Wqkv + PQ,                 C_, C_, QS);
    wt_kernel<<<dim3(C_ / 32, C_ / 32, L_), tb>>>(Wk, Wqkv + (size_t)C_ * C_,     Wqkv + PQ + (size_t)C_ * C_,     C_, C_, QS);
    wt_kernel<<<dim3(C_ / 32, C_ / 32, L_), tb>>>(Wv, Wqkv + (size_t)2 * C_ * C_, Wqkv + PQ + (size_t)2 * C_ * C_, C_, C_, QS);
    wt_kernel<<<dim3(C_ / 32, C_ / 32, L_), tb>>>(Wo, WoT, WoT + PW, C_, C_, (size_t)C_ * C_);
    wt_kernel<<<dim3(H_ / 32, C_ / 32, L_ * 2), tb>>>(W1, W1T, W1T + PW1, C_, H_, (size_t)C_ * H_);
    wt_kernel<<<dim3(C_ / 32, H_ / 32, L_ * 2), tb>>>(W2, W2T, W2T + PW2, H_, C_, (size_t)H_ * C_);
    wt_kernel<<<dim3(H_ / 32, (2 * C_) / 32, L_), tb>>>(Wl1, Wl1T, Wl1T + PL1, 2 * C_, H_, (size_t)2 * C_ * H_);
    wt_kernel<<<dim3(C_ / 32, H_ / 32, L_), tb>>>(Wl2, Wl2T, Wl2T + PL2, H_, C_, (size_t)H_ * C_);
    wt_kernel<<<dim3(V_ / 32, C_ / 32, 1), tb>>>(head_W, HT, HT + PHT, C_, V_, (size_t)C_ * V_);

    cudaFuncSetAttribute(hgemm_zb_kernel<OP_RELU, 1>, cudaFuncAttributeMaxDynamicSharedMemorySize, SMEM_BYTES);
    cudaFuncSetAttribute(hgemm_zb_kernel<OP_NONE, 0>, cudaFuncAttributeMaxDynamicSharedMemorySize, SMEM_BYTES);

    const int EW = SZ / 256;
    embed_kernel<<<EW, 256>>>(idx, emb, X);

    for (int l = 0; l < L_; l++) {
        const size_t wo = (size_t)l * C_ * C_;
        ln_kernel<0><<<BT, 256>>>(X, HS, nullptr, nullptr, ln1_g + (size_t)l * C_, ln1_b + (size_t)l * C_);
        mix_kernel<<<EW, 256>>>(HS, MIXb, MIXb + PA);
        gemm(OP_QKV, MIXb, MIXb + PA, Wqkv + (size_t)l * QS, Wqkv + PQ + (size_t)l * QS,
             nullptr, QKV, nullptr, nullptr, nullptr, BT, QW, C_, C_);
        scan1_kernel<<<(B_ * NCH * C_) / 256, 256>>>(QKV, PART);
        scan2_kernel<<<(B_ * C_) / 256, 256>>>(PART);
        scan3_kernel<<<(B_ * NCH * C_) / 256, 256>>>(QKV, PART, ST, STb, STb + PA);
        rs_kernel<<<EW, 256>>>(QKV, ST, RSb, RSb + PA);
        gemm(OP_ADD, RSb, RSb + PA, WoT + wo, WoT + PW + wo, X, X, nullptr, nullptr, nullptr, BT, C_, C_, C_);
        ln_kernel<1><<<BT, 256>>>(X, Hh, Hb, Hb + PA, ln2_g + (size_t)l * C_, ln2_b + (size_t)l * C_);
        route_kernel<<<BT / 8, 256>>>(Hh, w_conf + (size_t)l * E_ * C_,
                                      W_aff + (size_t)l * C_ * E_,
                                      shares + (size_t)l * E_, WIN, SCL);
        zero_cnt_kernel<<<1, 32>>>();
        compact_kernel<<<BT / 256, 256>>>(WIN);

        // gathers: experts 0/1 batched, expert 2 (concat) separate
        gatherB_kernel<<<dim3(BT / 8, 2), 256>>>(Hb, Hb + PA, GA, GA + PGA);
        gather2_kernel<<<BT / 8, 256>>>(Hb, Hb + PA, STb, STb + PA, GA2, GA2 + PG2);

        // first GEMMs: FFN experts 0/1 batched (Z=2, K=C); linear expert (K=2C)
        const size_t w1o = (size_t)l * 2 * H_ * C_;
        hgemm_zb_kernel<OP_RELU, 1><<<dim3(H_ / 128, BT / 128, 2), 256, SMEM_BYTES>>>(
            GA, GA + PGA, (size_t)SZ,
            W1T + w1o, W1T + PW1 + w1o,
            W1T + w1o + (size_t)H_ * C_, W1T + PW1 + w1o + (size_t)H_ * C_,
            nullptr, nullptr,
            nullptr, 0, FFb, FFb + PF, FE, H_, C_, C_);
        const size_t l1o = (size_t)l * H_ * 2 * C_;
        gemm(OP_RELU, GA2, GA2 + PG2, Wl1T + l1o, Wl1T + PL1 + l1o, nullptr, nullptr,
             FFb + 2 * FE, FFb + PF + 2 * FE, CNT + 2, BT, H_, 2 * C_, 2 * C_);

        // second GEMMs: all three experts batched (Z=3, K=H)
        const size_t w2o = (size_t)l * 2 * C_ * H_;
        const size_t l2o = (size_t)l * C_ * H_;
        hgemm_zb_kernel<OP_NONE, 0><<<dim3(C_ / 128, BT / 128, 3), 256, SMEM_BYTES>>>(
            FFb, FFb + PF, FE,
            W2T + w2o, W2T + PW2 + w2o,
            W2T + w2o + (size_t)C_ * H_, W2T + PW2 + w2o + (size_t)C_ * H_,
            Wl2T + l2o, Wl2T + PL2 + l2o,
            EC, (size_t)SZ, nullptr, nullptr, 0, C_, H_, H_);

        scatterB_kernel<<<dim3(BT / 8, 3), 256>>>(X, EC, SCL);
    }

    ln_kernel<1><<<BT, 256>>>(X, HS, HSb, HSb + PA, lnf_g, lnf_b);
    gemm(OP_NONE, HSb, HSb + PA, HT, HT + PHT, nullptr, (float*)d_out, nullptr, nullptr, nullptr, BT, V_, C_, C_);
}

// round 17
// speedup vs baseline: 1.4125x; 1.0008x over previous
#include <cuda_runtime.h>
#include <cuda_bf16.h>
#include <cstdint>
#include <math.h>

#define B_ 2
#define T_ 2048
#define BT 4096
#define C_ 1024
#define QW 3072
#define V_ 32000
#define L_ 4
#define E_ 3
#define H_ 4096
#define NCH 32
#define CHL 64
#define SZ (BT*C_)

typedef __nv_bfloat16 bf16;

// ---------------- static scratch (no allocations) ----------------
__device__ float g_X[SZ], g_HS[SZ], g_Hh[SZ];
__device__ float g_QKV[(size_t)BT * QW];
__device__ float g_EC[(size_t)E_ * SZ];
__device__ float g_PART[B_ * NCH * C_], g_SCL[BT];
__device__ int   g_CNT[E_];
__device__ int   g_LIST[E_][BT];

__device__ bf16 g_MIXb[2][SZ], g_RSb[2][SZ], g_Hb[2][SZ], g_STb[2][SZ], g_HSb[2][SZ];
__device__ bf16 g_GA[2][(size_t)2 * SZ];
__device__ bf16 g_GA2[2][(size_t)BT * 2 * C_];
__device__ bf16 g_FFb[2][(size_t)E_ * BT * H_];

__device__ bf16 g_Wqkv[2][(size_t)L_ * QW * C_];
__device__ bf16 g_WoT[2][(size_t)L_ * C_ * C_];
__device__ bf16 g_W1T[2][(size_t)L_ * 2 * H_ * C_], g_W2T[2][(size_t)L_ * 2 * C_ * H_];
__device__ bf16 g_Wl1T[2][(size_t)L_ * H_ * 2 * C_], g_Wl2T[2][(size_t)L_ * C_ * H_];
__device__ bf16 g_HT[2][(size_t)V_ * C_];

__device__ __forceinline__ void split2(float x, bf16& h, bf16& l) {
    h = __float2bfloat16(x);
    l = __float2bfloat16(x - __bfloat162float(h));
}

// ---------------- block reduce / LN ----------------
__device__ __forceinline__ float blockReduceSum(float val) {
    __shared__ float sh[8];
    int lane = threadIdx.x & 31, w = threadIdx.x >> 5;
#pragma unroll
    for (int o = 16; o > 0; o >>= 1) val += __shfl_xor_sync(0xffffffffu, val, o);
    if (lane == 0) sh[w] = val;
    __syncthreads();
    if (w == 0) {
        float v2 = (lane < 8) ? sh[lane] : 0.f;
#pragma unroll
        for (int o = 4; o > 0; o >>= 1) v2 += __shfl_xor_sync(0xffffffffu, v2, o);
        if (lane == 0) sh[0] = v2;
    }
    __syncthreads();
    float r = sh[0];
    __syncthreads();
    return r;
}

template <int EMIT>
__global__ __launch_bounds__(256) void ln_kernel(const float* __restrict__ x,
                                                 float* __restrict__ y,
                                                 bf16* __restrict__ yh, bf16* __restrict__ yl,
                                                 const float* __restrict__ g,
                                                 const float* __restrict__ b) {
    int row = blockIdx.x;
    const float* xr = x + (size_t)row * C_;
    int t = threadIdx.x;
    float v0 = xr[t], v1 = xr[t + 256], v2 = xr[t + 512], v3 = xr[t + 768];
    float s = blockReduceSum(v0 + v1 + v2 + v3);
    float mean = s * (1.f / C_);
    float d0 = v0 - mean, d1 = v1 - mean, d2 = v2 - mean, d3 = v3 - mean;
    float s2 = blockReduceSum(d0 * d0 + d1 * d1 + d2 * d2 + d3 * d3);
    float inv = rsqrtf(s2 * (1.f / C_) + 1e-5f);
    size_t base = (size_t)row * C_;
    float o0 = d0 * inv * g[t]       + b[t];
    float o1 = d1 * inv * g[t + 256] + b[t + 256];
    float o2 = d2 * inv * g[t + 512] + b[t + 512];
    float o3 = d3 * inv * g[t + 768] + b[t + 768];
    y[base + t] = o0; y[base + t + 256] = o1; y[base + t + 512] = o2; y[base + t + 768] = o3;
    if (EMIT) {
        split2(o0, yh[base + t],       yl[base + t]);
        split2(o1, yh[base + t + 256], yl[base + t + 256]);
        split2(o2, yh[base + t + 512], yl[base + t + 512]);
        split2(o3, yh[base + t + 768], yl[base + t + 768]);
    }
}

// ---------------- elementwise ----------------
__global__ __launch_bounds__(256) void embed_kernel(const int* __restrict__ idx,
                                                    const float* __restrict__ emb,
                                                    float* __restrict__ X) {
    int i = blockIdx.x * 256 + threadIdx.x;
    int row = i >> 10, c = i & 1023;
    X[i] = emb[(size_t)idx[row] * C_ + c];
}

__global__ __launch_bounds__(256) void mix_kernel(const float* __restrict__ hs,
                                                  bf16* __restrict__ mh, bf16* __restrict__ ml) {
    int i = blockIdx.x * 256 + threadIdx.x;
    int row = i >> 10, t = row & (T_ - 1);
    float prev = (t == 0) ? 0.f : hs[i - C_];
    split2(0.5f * (hs[i] + prev), mh[i], ml[i]);
}

// ---------------- RWKV scan (k,v from strided QKV) ----------------
__global__ __launch_bounds__(256) void scan1_kernel(const float* __restrict__ qkv,
                                                    float* __restrict__ part) {
    int g = blockIdx.x * 256 + threadIdx.x;
    int c = g & (C_ - 1), ch = (g >> 10) & (NCH - 1), b = g >> 15;
    size_t row = (size_t)(b * T_ + ch * CHL);
    float s = 0.f;
#pragma unroll 4
    for (int j = 0; j < CHL; j++) {
        const float* q = qkv + (row + j) * QW;
        s += q[C_ + c] * q[2 * C_ + c];
    }
    part[g] = s;
}

__global__ __launch_bounds__(256) void scan2_kernel(float* __restrict__ part) {
    int g = blockIdx.x * 256 + threadIdx.x;
    int c = g & (C_ - 1), b = g >> 10;
    float run = 0.f;
#pragma unroll
    for (int ch = 0; ch < NCH; ch++) {
        size_t i = ((size_t)(b * NCH + ch)) * C_ + c;
        float tv = part[i]; part[i] = run; run += tv;
    }
}

// scan3 fused with rs: emits state hi/lo planes AND (r * state) hi/lo planes.
__global__ __launch_bounds__(256) void scan3_kernel(const float* __restrict__ qkv,
                                                    const float* __restrict__ part,
                                                    bf16* __restrict__ sh, bf16* __restrict__ sl,
                                                    bf16* __restrict__ rh, bf16* __restrict__ rl) {
    int g = blockIdx.x * 256 + threadIdx.x;
    int c = g & (C_ - 1), ch = (g >> 10) & (NCH - 1), b = g >> 15;
    size_t row = (size_t)(b * T_ + ch * CHL);
    size_t obase = row * C_ + c;
    float run = part[g];
#pragma unroll 4
    for (int j = 0; j < CHL; j++) {
        const float* q = qkv + (row + j) * QW;
        run += q[C_ + c] * q[2 * C_ + c];
        float v = run / (float)(ch * CHL + j + 1);
        split2(v, sh[obase], sl[obase]);
        float r = q[c];
        split2(r * v, rh[obase], rl[obase]);
        obase += C_;
    }
}

// ---------------- router (fp32) with fused compaction ----------------
__global__ void zero_cnt_kernel() {
    if (threadIdx.x < E_) g_CNT[threadIdx.x] = 0;
}

__global__ __launch_bounds__(256) void route_kernel(const float* __restrict__ Hh,
                                                    const float* __restrict__ wconf,
                                                    const float* __restrict__ waff,
                                                    const float* __restrict__ shares,
                                                    float* __restrict__ scale) {
    int token = blockIdx.x * 8 + (threadIdx.x >> 5);
    int lane = threadIdx.x & 31;
    const float* h = Hh + (size_t)token * C_;
    float sc0 = 0, sc1 = 0, sc2 = 0, sa0 = 0, sa1 = 0, sa2 = 0;
    for (int c = lane; c < C_; c += 32) {
        float hv = h[c];
        sc0 = fmaf(hv, wconf[c], sc0);
        sc1 = fmaf(hv, wconf[C_ + c], sc1);
        sc2 = fmaf(hv, wconf[2 * C_ + c], sc2);
        sa0 = fmaf(hv, waff[c * E_ + 0], sa0);
        sa1 = fmaf(hv, waff[c * E_ + 1], sa1);
        sa2 = fmaf(hv, waff[c * E_ + 2], sa2);
    }
#pragma unroll
    for (int o = 16; o > 0; o >>= 1) {
        sc0 += __shfl_xor_sync(0xffffffffu, sc0, o);
        sc1 += __shfl_xor_sync(0xffffffffu, sc1, o);
        sc2 += __shfl_xor_sync(0xffffffffu, sc2, o);
        sa0 += __shfl_xor_sync(0xffffffffu, sa0, o);
        sa1 += __shfl_xor_sync(0xffffffffu, sa1, o);
        sa2 += __shfl_xor_sync(0xffffffffu, sa2, o);
    }
    if (lane == 0) {
        float c0 = 1.f / (1.f + expf(-sc0));
        float c1 = 1.f / (1.f + expf(-sc1));
        float c2 = 1.f / (1.f + expf(-sc2));
        float b0 = c0 * shares[0] + sa0;
        float b1 = c1 * shares[1] + sa1;
        float b2 = c2 * shares[2] + sa2;
        int w = 0; float bb = b0, cw = c0;
        if (b1 > bb) { bb = b1; w = 1; cw = c1; }
        if (b2 > bb) { bb = b2; w = 2; cw = c2; }
        scale[token] = cw / (cw + 1e-6f);
        int pos = atomicAdd(&g_CNT[w], 1);
        g_LIST[w][pos] = token;
    }
}

// ---------------- MoE gathers / scatter ----------------
__global__ __launch_bounds__(256) void gatherB_kernel(const bf16* __restrict__ sh,
                                                      const bf16* __restrict__ sl,
                                                      bf16* __restrict__ dh, bf16* __restrict__ dl) {
    int e = blockIdx.y;
    int row = blockIdx.x * 8 + (threadIdx.x >> 5);
    if (row >= g_CNT[e]) return;
    int lane = threadIdx.x & 31;
    int tok = g_LIST[e][row];
    const uint4* s0 = (const uint4*)(sh + (size_t)tok * C_);
    const uint4* s1 = (const uint4*)(sl + (size_t)tok * C_);
    uint4* d0 = (uint4*)(dh + ((size_t)e * BT + row) * C_);
    uint4* d1 = (uint4*)(dl + ((size_t)e * BT + row) * C_);
    for (int i = lane; i < C_ / 8; i += 32) { d0[i] = s0[i]; d1[i] = s1[i]; }
}

__global__ __launch_bounds__(256) void gather2_kernel(const bf16* __restrict__ hh,
                                                      const bf16* __restrict__ hl,
                                                      const bf16* __restrict__ sh,
                                                      const bf16* __restrict__ sl,
                                                      bf16* __restrict__ dh, bf16* __restrict__ dl) {
    int row = blockIdx.x * 8 + (threadIdx.x >> 5);
    if (row >= g_CNT[2]) return;
    int lane = threadIdx.x & 31;
    int tok = g_LIST[2][row];
    const uint4* h0 = (const uint4*)(hh + (size_t)tok * C_);
    const uint4* h1 = (const uint4*)(hl + (size_t)tok * C_);
    const uint4* s0 = (const uint4*)(sh + (size_t)tok * C_);
    const uint4* s1 = (const uint4*)(sl + (size_t)tok * C_);
    uint4* d0 = (uint4*)(dh + (size_t)row * 2 * C_);
    uint4* d1 = (uint4*)(dl + (size_t)row * 2 * C_);
    const int nv = C_ / 8;
    for (int i = lane; i < nv; i += 32) {
        d0[i] = h0[i];      d1[i] = h1[i];
        d0[nv + i] = s0[i]; d1[nv + i] = s1[i];
    }
}

__global__ __launch_bounds__(256) void scatterB_kernel(float* __restrict__ X,
                                                       const float* __restrict__ EC,
                                                       const float* __restrict__ scale) {
    int e = blockIdx.y;
    int row = blockIdx.x * 8 + (threadIdx.x >> 5);
    if (row >= g_CNT[e]) return;
    int lane = threadIdx.x & 31;
    int tok = g_LIST[e][row];
    float sc = scale[tok];
    const float4* s = (const float4*)(EC + ((size_t)e * BT + row) * C_);
    float4* d = (float4*)(X + (size_t)tok * C_);
    for (int i = lane; i < C_ / 4; i += 32) {
        float4 v = s[i]; float4 o = d[i];
        o.x += v.x * sc; o.y += v.y * sc; o.z += v.z * sc; o.w += v.w * sc;
        d[i] = o;
    }
}

// ---- weight transpose+split: [z][K][N] f32 -> [z·ostride][N][K] bf16 hi/lo.
// 64(k) x 32(n) tile; 128B-coalesced reads AND writes (bf16x2 pairs).
__global__ __launch_bounds__(256) void wt_kernel(const float* __restrict__ in,
                                                 bf16* __restrict__ oh, bf16* __restrict__ ol,
                                                 int K, int N, size_t ostride) {
    __shared__ float t[64][33];
    int z = blockIdx.z;
    const float* ip = in + (size_t)z * K * N;
    int n0 = blockIdx.x * 32, k0 = blockIdx.y * 64;
    int tx = threadIdx.x, ty = threadIdx.y;
#pragma unroll
    for (int j = 0; j < 64; j += 8)
        t[ty + j][tx] = ip[(size_t)(k0 + ty + j) * N + n0 + tx];
    __syncthreads();
    size_t ob = (size_t)z * ostride;
#pragma unroll
    for (int i = 0; i < 32; i += 8) {
        int n = ty + i;
        float v0 = t[2 * tx][n], v1 = t[2 * tx + 1][n];
        bf16 h0, l0, h1, l1;
        split2(v0, h0, l0); split2(v1, h1, l1);
        size_t o = ob + (size_t)(n0 + n) * K + k0 + 2 * tx;
        *(__nv_bfloat162*)&oh[o] = __halves2bfloat162(h0, h1);
        *(__nv_bfloat162*)&ol[o] = __halves2bfloat162(l0, l1);
    }
}

// ---------------------------------------------------------------------------
// bf16x3 tensor-core GEMM — round-10 inner loop (unchanged).
// ---------------------------------------------------------------------------
enum { OP_NONE = 0, OP_RELU = 2, OP_ADD = 3, OP_QKV = 5 };

#define PADK 40
#define PLANE_B (128 * PADK * 2)
#define SMEM_BYTES (8 * PLANE_B)

__device__ __forceinline__ uint32_t s2u(const void* p) {
    uint32_t a;
    asm("{ .reg .u64 t; cvta.to.shared.u64 t, %1; cvt.u32.u64 %0, t; }" : "=r"(a) : "l"(p));
    return a;
}
__device__ __forceinline__ void cpa16(uint32_t d, const void* s) {
    asm volatile("cp.async.cg.shared.global [%0], [%1], 16;" :: "r"(d), "l"(s));
}
__device__ __forceinline__ void ldsm4(uint32_t* r, uint32_t a) {
    asm volatile("ldmatrix.sync.aligned.m8n8.x4.shared.b16 {%0,%1,%2,%3}, [%4];"
                 : "=r"(r[0]), "=r"(r[1]), "=r"(r[2]), "=r"(r[3]) : "r"(a));
}
__device__ __forceinline__ void mma_bf16(float* c, const uint32_t* a, uint32_t b0, uint32_t b1) {
    asm volatile(
        "mma.sync.aligned.m16n8k16.row.col.f32.bf16.bf16.f32 "
        "{%0,%1,%2,%3}, {%4,%5,%6,%7}, {%8,%9}, {%0,%1,%2,%3};"
        : "+f"(c[0]), "+f"(c[1]), "+f"(c[2]), "+f"(c[3])
        : "r"(a[0]), "r"(a[1]), "r"(a[2]), "r"(a[3]), "r"(b0), "r"(b1));
}

template <int OP, int WB>
__device__ __forceinline__ void gemm_body(
        const bf16* Ahp, const bf16* Alp,
        const bf16* Bhp, const bf16* Blp,
        const float* Cin, float* Cout,
        bf16* Eh, bf16* El,
        int m0, int n0, int N, int K, int ldb, char* smem) {
    const uint32_t uS = s2u(smem);
    const int tid = threadIdx.x, wid = tid >> 5, lane = tid & 31;
    const int nk = K >> 5;

    const int lrow = tid >> 1, lhalf = tid & 1;
    const bf16* gA[2] = { Ahp + (size_t)(m0 + lrow) * K + lhalf * 16,
                          Alp + (size_t)(m0 + lrow) * K + lhalf * 16 };
    const bf16* gB[2] = { Bhp + (size_t)(n0 + lrow) * ldb + lhalf * 16,
                          Blp + (size_t)(n0 + lrow) * ldb + lhalf * 16 };
    const uint32_t sOff = (lrow * PADK + lhalf * 16) * 2;

#define LOAD_STAGE(s, kt) do {                                            \
        size_t ko = (size_t)(kt) * 32;                                    \
        uint32_t sb = uS + (s) * 4 * PLANE_B + sOff;                      \
        cpa16(sb,                gA[0] + ko);                             \
        cpa16(sb + 16,           gA[0] + ko + 8);                         \
        cpa16(sb + PLANE_B,      gA[1] + ko);                             \
        cpa16(sb + PLANE_B + 16, gA[1] + ko + 8);                         \
        cpa16(sb + 2 * PLANE_B,      gB[0] + ko);                         \
        cpa16(sb + 2 * PLANE_B + 16, gB[0] + ko + 8);                     \
        cpa16(sb + 3 * PLANE_B,      gB[1] + ko);                         \
        cpa16(sb + 3 * PLANE_B + 16, gB[1] + ko + 8);                     \
        asm volatile("cp.async.commit_group;" ::: "memory");              \
    } while (0)

    float acc[4][4][4];
#pragma unroll
    for (int i = 0; i < 4; i++)
#pragma unroll
        for (int j = 0; j < 4; j++)
#pragma unroll
            for (int q = 0; q < 4; q++) acc[i][j][q] = 0.f;

    const int mB = (wid & 1) * 64, nB = (wid >> 1) * 32;
    const int lane16 = lane & 15, laneHi = lane >> 4;
    const uint32_t aFrag = ((mB + lane16) * PADK + laneHi * 8) * 2;
    const uint32_t bFrag = ((nB + lane16) * PADK + laneHi * 8) * 2;

    LOAD_STAGE(0, 0);

    for (int kt = 0; kt < nk; kt++) {
        const int s = kt & 1;
        asm volatile("cp.async.wait_group 0;" ::: "memory");
        __syncthreads();
        if (kt + 1 < nk) LOAD_STAGE(s ^ 1, kt + 1);

        const uint32_t pAh = uS + s * 4 * PLANE_B;
        const uint32_t pAl = pAh + PLANE_B;
        const uint32_t pBh = pAh + 2 * PLANE_B;
        const uint32_t pBl = pAh + 3 * PLANE_B;
#pragma unroll
        for (int kk = 0; kk < 2; kk++) {
            const uint32_t k0b = kk * 32;
            uint32_t ah[4][4], al[4][4], bh[2][4], bl[2][4];
#pragma unroll
            for (int i = 0; i < 4; i++) {
                ldsm4(ah[i], pAh + aFrag + k0b + i * (16 * PADK * 2));
                ldsm4(al[i], pAl + aFrag + k0b + i * (16 * PADK * 2));
            }
#pragma unroll
            for (int jj = 0; jj < 2; jj++) {
                ldsm4(bh[jj], pBh + bFrag + k0b + jj * (16 * PADK * 2));
                ldsm4(bl[jj], pBl + bFrag + k0b + jj * (16 * PADK * 2));
            }
#pragma unroll
            for (int j = 0; j < 4; j++) {
                const int jj = j >> 1, t = j & 1;
                const uint32_t bh0 = bh[jj][t], bh1 = bh[jj][2 + t];
                const uint32_t bl0 = bl[jj][t], bl1 = bl[jj][2 + t];
#pragma unroll
                for (int i = 0; i < 4; i++) {
                    mma_bf16(acc[i][j], ah[i], bh0, bh1);
                    mma_bf16(acc[i][j], ah[i], bl0, bl1);
                    mma_bf16(acc[i][j], al[i], bh0, bh1);
                }
            }
        }
        __syncthreads();
    }
#undef LOAD_STAGE

    const int lr = lane >> 2, lc = lane & 3;
    const bool qkvsig = (OP == OP_QKV) && (n0 < C_);
#pragma unroll
    for (int i = 0; i < 4; i++)
#pragma unroll
        for (int j = 0; j < 4; j++)
#pragma unroll
            for (int h = 0; h < 2; h++) {
                int row = m0 + mB + i * 16 + lr + h * 8;
                int col = n0 + nB + j * 8 + lc * 2;
                float v0 = acc[i][j][h * 2 + 0];
                float v1 = acc[i][j][h * 2 + 1];
                if (OP == OP_QKV) {
                    if (qkvsig) { v0 = 1.f / (1.f + expf(-v0)); v1 = 1.f / (1.f + expf(-v1)); }
                } else if (OP == OP_RELU) {
                    v0 = fmaxf(v0, 0.f); v1 = fmaxf(v1, 0.f);
                } else if (OP == OP_ADD) {
                    float2 o = *(const float2*)&Cin[(size_t)row * N + col];
                    v0 += o.x; v1 += o.y;
                }
                if (WB) {
                    bf16 h0, l0, h1, l1;
                    split2(v0, h0, l0); split2(v1, h1, l1);
                    size_t o = (size_t)row * N + col;
                    *(__nv_bfloat162*)&Eh[o] = __halves2bfloat162(h0, h1);
                    *(__nv_bfloat162*)&El[o] = __halves2bfloat162(l0, l1);
                } else {
                    *(float2*)&Cout[(size_t)row * N + col] = make_float2(v0, v1);
                }
            }
}

template <int OP, int WB>
__global__ __launch_bounds__(256) void hgemm_kernel(
        const bf16* __restrict__ Ahp, const bf16* __restrict__ Alp,
        const bf16* __restrict__ Bhp, const bf16* __restrict__ Blp,
        const float* __restrict__ Cin, float* __restrict__ Cout,
        bf16* __restrict__ Eh, bf16* __restrict__ El,
        const int* __restrict__ cntp,
        int M, int N, int K, int ldb) {
    const int m0 = blockIdx.y * 128, n0 = blockIdx.x * 128;
    if (cntp && m0 >= *cntp) return;
    extern __shared__ __align__(16) char smem[];
    gemm_body<OP, WB>(Ahp, Alp, Bhp, Blp, Cin, Cout, Eh, El, m0, n0, N, K, ldb, smem);
}

template <int OP, int WB>
__global__ __launch_bounds__(256) void hgemm_zb_kernel(
        const bf16* __restrict__ Ahp, const bf16* __restrict__ Alp, size_t aStr,
        const bf16* __restrict__ B0h, const bf16* __restrict__ B0l,
        const bf16* __restrict__ B1h, const bf16* __restrict__ B1l,
        const bf16* __restrict__ B2h, const bf16* __restrict__ B2l,
        float* __restrict__ Cout, size_t cStr,
        bf16* __restrict__ Eh, bf16* __restrict__ El, size_t eStr,
        int N, int K, int ldb) {
    const int z = blockIdx.z;
    const int m0 = blockIdx.y * 128, n0 = blockIdx.x * 128;
    if (m0 >= g_CNT[z]) return;
    const bf16* Bh = (z == 0) ? B0h : ((z == 1) ? B1h : B2h);
    const bf16* Bl = (z == 0) ? B0l : ((z == 1) ? B1l : B2l);
    extern __shared__ __align__(16) char smem[];
    gemm_body<OP, WB>(Ahp + (size_t)z * aStr, Alp + (size_t)z * aStr, Bh, Bl,
                      nullptr, Cout ? Cout + (size_t)z * cStr : nullptr,
                      Eh ? Eh + (size_t)z * eStr : nullptr,
                      El ? El + (size_t)z * eStr : nullptr,
                      m0, n0, N, K, ldb, smem);
}

static void gemm(int op, const bf16* Ah, const bf16* Al, const bf16* Bh, const bf16* Bl,
                 const float* Cin, float* Cout, bf16* Eh, bf16* El, const int* cntp,
                 int M, int N, int K, int ldb) {
    dim3 grid(N / 128, M / 128), block(256);
    switch (op) {
        case OP_NONE:
            cudaFuncSetAttribute(hgemm_kernel<OP_NONE, 0>, cudaFuncAttributeMaxDynamicSharedMemorySize, SMEM_BYTES);
            hgemm_kernel<OP_NONE, 0><<<grid, block, SMEM_BYTES>>>(Ah, Al, Bh, Bl, Cin, Cout, Eh, El, cntp, M, N, K, ldb);
            break;
        case OP_QKV:
            cudaFuncSetAttribute(hgemm_kernel<OP_QKV, 0>, cudaFuncAttributeMaxDynamicSharedMemorySize, SMEM_BYTES);
            hgemm_kernel<OP_QKV, 0><<<grid, block, SMEM_BYTES>>>(Ah, Al, Bh, Bl, Cin, Cout, Eh, El, cntp, M, N, K, ldb);
            break;
        case OP_ADD:
            cudaFuncSetAttribute(hgemm_kernel<OP_ADD, 0>, cudaFuncAttributeMaxDynamicSharedMemorySize, SMEM_BYTES);
            hgemm_kernel<OP_ADD, 0><<<grid, block, SMEM_BYTES>>>(Ah, Al, Bh, Bl, Cin, Cout, Eh, El, cntp, M, N, K, ldb);
            break;
        case OP_RELU:
            cudaFuncSetAttribute(hgemm_kernel<OP_RELU, 1>, cudaFuncAttributeMaxDynamicSharedMemorySize, SMEM_BYTES);
            hgemm_kernel<OP_RELU, 1><<<grid, block, SMEM_BYTES>>>(Ah, Al, Bh, Bl, Cin, Cout, Eh, El, cntp, M, N, K, ldb);
            break;
    }
}

// ---------------- host orchestration ----------------
extern "C" void kernel_launch(void* const* d_in, const int* in_sizes, int n_in,
                              void* d_out, int out_size) {
    (void)in_sizes; (void)n_in; (void)out_size;
    const int*   idx    = (const int*)d_in[0];
    const float* shares = (const float*)d_in[1];
    const float* emb    = (const float*)d_in[2];
    const float* ln1_g  = (const float*)d_in[3];
    const float* ln1_b  = (const float*)d_in[4];
    const float* ln2_g  = (const float*)d_in[5];
    const float* ln2_b  = (const float*)d_in[6];
    const float* Wr     = (const float*)d_in[7];
    const float* Wk     = (const float*)d_in[8];
    const float* Wv     = (const float*)d_in[9];
    const float* Wo     = (const float*)d_in[10];
    const float* W1     = (const float*)d_in[11];
    const float* W2     = (const float*)d_in[12];
    const float* w_conf = (const float*)d_in[13];
    const float* Wl1    = (const float*)d_in[14];
    const float* Wl2    = (const float*)d_in[15];
    /* d_in[16] = W_diff unused */
    const float* W_aff  = (const float*)d_in[17];
    const float* lnf_g  = (const float*)d_in[18];
    const float* lnf_b  = (const float*)d_in[19];
    const float* head_W = (const float*)d_in[20];

    float *X, *HS, *Hh, *QKV, *EC, *PART, *SCL;
    int *CNT;
    cudaGetSymbolAddress((void**)&X, g_X);     cudaGetSymbolAddress((void**)&HS, g_HS);
    cudaGetSymbolAddress((void**)&Hh, g_Hh);
    cudaGetSymbolAddress((void**)&QKV, g_QKV); cudaGetSymbolAddress((void**)&EC, g_EC);
    cudaGetSymbolAddress((void**)&PART, g_PART);
    cudaGetSymbolAddress((void**)&SCL, g_SCL);
    cudaGetSymbolAddress((void**)&CNT, g_CNT);
    bf16 *MIXb, *RSb, *Hb, *STb, *HSb, *FFb, *GA, *GA2;
    cudaGetSymbolAddress((void**)&MIXb, g_MIXb); cudaGetSymbolAddress((void**)&RSb, g_RSb);
    cudaGetSymbolAddress((void**)&Hb, g_Hb);     cudaGetSymbolAddress((void**)&STb, g_STb);
    cudaGetSymbolAddress((void**)&HSb, g_HSb);   cudaGetSymbolAddress((void**)&FFb, g_FFb);
    cudaGetSymbolAddress((void**)&GA, g_GA);     cudaGetSymbolAddress((void**)&GA2, g_GA2);
    bf16 *Wqkv, *WoT, *W1T, *W2T, *Wl1T, *Wl2T, *HT;
    cudaGetSymbolAddress((void**)&Wqkv, g_Wqkv); cudaGetSymbolAddress((void**)&WoT, g_WoT);
    cudaGetSymbolAddress((void**)&W1T, g_W1T);   cudaGetSymbolAddress((void**)&W2T, g_W2T);
    cudaGetSymbolAddress((void**)&Wl1T, g_Wl1T); cudaGetSymbolAddress((void**)&Wl2T, g_Wl2T);
    cudaGetSymbolAddress((void**)&HT, g_HT);

    const size_t PQ  = (size_t)L_ * QW * C_;
    const size_t PW  = (size_t)L_ * C_ * C_;
    const size_t PW1 = (size_t)L_ * 2 * H_ * C_;
    const size_t PW2 = (size_t)L_ * 2 * C_ * H_;
    const size_t PL1 = (size_t)L_ * H_ * 2 * C_;
    const size_t PL2 = (size_t)L_ * C_ * H_;
    const size_t PHT = (size_t)V_ * C_;
    const size_t PA  = (size_t)SZ;
    const size_t PGA = (size_t)2 * SZ;
    const size_t PG2 = (size_t)BT * 2 * C_;
    const size_t PF  = (size_t)E_ * BT * H_;
    const size_t FE  = (size_t)BT * H_;

    dim3 tb(32, 8);
    const size_t QS = (size_t)QW * C_;
    wt_kernel<<<dim3(C_ / 32, C_ / 64, L_), tb>>>(Wr, Wqkv,                       Wqkv + PQ,                       C_, C_, QS);
    wt_kernel<<<dim3(C_ / 32, C_ / 64, L_), tb>>>(Wk, Wqkv + (size_t)C_ * C_,     Wqkv + PQ + (size_t)C_ * C_,     C_, C_, QS);
    wt_kernel<<<dim3(C_ / 32, C_ / 64, L_), tb>>>(Wv, Wqkv + (size_t)2 * C_ * C_, Wqkv + PQ + (size_t)2 * C_ * C_, C_, C_, QS);
    wt_kernel<<<dim3(C_ / 32, C_ / 64, L_), tb>>>(Wo, WoT, WoT + PW, C_, C_, (size_t)C_ * C_);
    wt_kernel<<<dim3(H_ / 32, C_ / 64, L_ * 2), tb>>>(W1, W1T, W1T + PW1, C_, H_, (size_t)C_ * H_);
    wt_kernel<<<dim3(C_ / 32, H_ / 64, L_ * 2), tb>>>(W2, W2T, W2T + PW2, H_, C_, (size_t)H_ * C_);
    wt_kernel<<<dim3(H_ / 32, (2 * C_) / 64, L_), tb>>>(Wl1, Wl1T, Wl1T + PL1, 2 * C_, H_, (size_t)2 * C_ * H_);
    wt_kernel<<<dim3(C_ / 32, H_ / 64, L_), tb>>>(Wl2, Wl2T, Wl2T + PL2, H_, C_, (size_t)H_ * C_);
    wt_kernel<<<dim3(V_ / 32, C_ / 64, 1), tb>>>(head_W, HT, HT + PHT, C_, V_, (size_t)C_ * V_);

    cudaFuncSetAttribute(hgemm_zb_kernel<OP_RELU, 1>, cudaFuncAttributeMaxDynamicSharedMemorySize, SMEM_BYTES);
    cudaFuncSetAttribute(hgemm_zb_kernel<OP_NONE, 0>, cudaFuncAttributeMaxDynamicSharedMemorySize, SMEM_BYTES);

    const int EW = SZ / 256;
    embed_kernel<<<EW, 256>>>(idx, emb, X);

    for (int l = 0; l < L_; l++) {
        const size_t wo = (size_t)l * C_ * C_;
        ln_kernel<0><<<BT, 256>>>(X, HS, nullptr, nullptr, ln1_g + (size_t)l * C_, ln1_b + (size_t)l * C_);
        mix_kernel<<<EW, 256>>>(HS, MIXb, MIXb + PA);
        gemm(OP_QKV, MIXb, MIXb + PA, Wqkv + (size_t)l * QS, Wqkv + PQ + (size_t)l * QS,
             nullptr, QKV, nullptr, nullptr, nullptr, BT, QW, C_, C_);
        scan1_kernel<<<(B_ * NCH * C_) / 256, 256>>>(QKV, PART);
        scan2_kernel<<<(B_ * C_) / 256, 256>>>(PART);
        scan3_kernel<<<(B_ * NCH * C_) / 256, 256>>>(QKV, PART, STb, STb + PA, RSb, RSb + PA);
        gemm(OP_ADD, RSb, RSb + PA, WoT + wo, WoT + PW + wo, X, X, nullptr, nullptr, nullptr, BT, C_, C_, C_);
        ln_kernel<1><<<BT, 256>>>(X, Hh, Hb, Hb + PA, ln2_g + (size_t)l * C_, ln2_b + (size_t)l * C_);
        zero_cnt_kernel<<<1, 32>>>();
        route_kernel<<<BT / 8, 256>>>(Hh, w_conf + (size_t)l * E_ * C_,
                                      W_aff + (size_t)l * C_ * E_,
                                      shares + (size_t)l * E_, SCL);

        gatherB_kernel<<<dim3(BT / 8, 2), 256>>>(Hb, Hb + PA, GA, GA + PGA);
        gather2_kernel<<<BT / 8, 256>>>(Hb, Hb + PA, STb, STb + PA, GA2, GA2 + PG2);

        const size_t w1o = (size_t)l * 2 * H_ * C_;
        hgemm_zb_kernel<OP_RELU, 1><<<dim3(H_ / 128, BT / 128, 2), 256, SMEM_BYTES>>>(
            GA, GA + PGA, (size_t)SZ,
            W1T + w1o, W1T + PW1 + w1o,
            W1T + w1o + (size_t)H_ * C_, W1T + PW1 + w1o + (size_t)H_ * C_,
            nullptr, nullptr,
            nullptr, 0, FFb, FFb + PF, FE, H_, C_, C_);
        const size_t l1o = (size_t)l * H_ * 2 * C_;
        gemm(OP_RELU, GA2, GA2 + PG2, Wl1T + l1o, Wl1T + PL1 + l1o, nullptr, nullptr,
             FFb + 2 * FE, FFb + PF + 2 * FE, CNT + 2, BT, H_, 2 * C_, 2 * C_);

        const size_t w2o = (size_t)l * 2 * C_ * H_;
        const size_t l2o = (size_t)l * C_ * H_;
        hgemm_zb_kernel<OP_NONE, 0><<<dim3(C_ / 128, BT / 128, 3), 256, SMEM_BYTES>>>(
            FFb, FFb + PF, FE,
            W2T + w2o, W2T + PW2 + w2o,
            W2T + w2o + (size_t)C_ * H_, W2T + PW2 + w2o + (size_t)C_ * H_,
            Wl2T + l2o, Wl2T + PL2 + l2o,
            EC, (size_t)SZ, nullptr, nullptr, 0, C_, H_, H_);

        scatterB_kernel<<<dim3(BT / 8, 3), 256>>>(X, EC, SCL);
    }

    ln_kernel<1><<<BT, 256>>>(X, HS, HSb, HSb + PA, lnf_g, lnf_b);
    gemm(OP_NONE, HSb, HSb + PA, HT, HT + PHT, nullptr, (float*)d_out, nullptr, nullptr, nullptr, BT, V_, C_, C_);
}